// round 1
// baseline (speedup 1.0000x reference)
#include <cuda_runtime.h>
#include <math.h>

// Problem constants (fixed by setup_inputs)
#define B_    2
#define S_    1024
#define ROWS  (B_*S_)       // 2048
#define H_    1536
#define F_    8960
#define L_    2
#define NH    12
#define NKV   2
#define DH    128
#define QD    (NH*DH)       // 1536
#define KVD   (NKV*DH)      // 256
#define EPS_  1e-6f

// Scratch (device globals: no allocation allowed)
__device__ float g_x  [ROWS*H_];
__device__ float g_h  [ROWS*H_];
__device__ float g_q  [ROWS*QD];
__device__ float g_k  [ROWS*KVD];
__device__ float g_v  [ROWS*KVD];
__device__ float g_att[ROWS*QD];
__device__ float g_gate[(size_t)ROWS*F_];
__device__ float g_up  [(size_t)ROWS*F_];

// ---------------- embedding gather ----------------
__global__ void embed_kernel(const int* __restrict__ ids,
                             const float* __restrict__ emb,
                             float* __restrict__ x) {
    int row = blockIdx.x;
    int id  = ids[row];
    const float* e = emb + (size_t)id * H_;
    float* xr = x + (size_t)row * H_;
    for (int i = threadIdx.x; i < H_; i += blockDim.x) xr[i] = e[i];
}

// ---------------- rmsnorm ----------------
__global__ void rmsnorm_kernel(const float* __restrict__ x,
                               const float* __restrict__ w,
                               float* __restrict__ out) {
    int row = blockIdx.x;
    const float* xr = x + (size_t)row * H_;
    int tid = threadIdx.x;            // 256
    float s = 0.f;
    for (int i = tid; i < H_; i += 256) { float v = xr[i]; s += v * v; }
    __shared__ float red[256];
    red[tid] = s; __syncthreads();
    for (int off = 128; off > 0; off >>= 1) {
        if (tid < off) red[tid] += red[tid + off];
        __syncthreads();
    }
    float rs = rsqrtf(red[0] / (float)H_ + EPS_);
    float* o = out + (size_t)row * H_;
    for (int i = tid; i < H_; i += 256) o[i] = xr[i] * rs * w[i];
}

// ---------------- SGEMM: C[M,N] = A[M,K] @ B[K,N] (+bias) (+residual) ----------------
// BM=BN=128, BK=8, 256 threads, 8x8 per-thread tile. Requires M%128==0, N%128==0, K%8==0.
template<bool BIAS, bool RES>
__global__ void __launch_bounds__(256, 2)
sgemm_kernel(int M, int N, int K,
             const float* __restrict__ A, const float* __restrict__ Bm,
             const float* __restrict__ bias, const float* __restrict__ res,
             float* __restrict__ C) {
    __shared__ float As[8][128];
    __shared__ float Bs[8][128];
    const int tid = threadIdx.x;
    const int tx = tid % 16, ty = tid / 16;
    const int bx = blockIdx.x, by = blockIdx.y;

    const float* Ab = A + (size_t)by * 128 * K;
    const float* Bb = Bm + (size_t)bx * 128;

    const int arow = tid >> 1, acol = (tid & 1) * 4;
    const int brow = tid >> 5, bcol = (tid & 31) * 4;

    float acc[8][8];
    #pragma unroll
    for (int i = 0; i < 8; i++)
        #pragma unroll
        for (int j = 0; j < 8; j++) acc[i][j] = 0.f;

    for (int k0 = 0; k0 < K; k0 += 8) {
        float4 av = *(const float4*)(Ab + (size_t)arow * K + k0 + acol);
        As[acol + 0][arow] = av.x;
        As[acol + 1][arow] = av.y;
        As[acol + 2][arow] = av.z;
        As[acol + 3][arow] = av.w;
        float4 bv = *(const float4*)(Bb + (size_t)(k0 + brow) * N + bcol);
        *(float4*)&Bs[brow][bcol] = bv;
        __syncthreads();
        #pragma unroll
        for (int k = 0; k < 8; k++) {
            float ar[8], br[8];
            #pragma unroll
            for (int i = 0; i < 8; i++) ar[i] = As[k][ty * 8 + i];
            #pragma unroll
            for (int j = 0; j < 8; j++) br[j] = Bs[k][tx * 8 + j];
            #pragma unroll
            for (int i = 0; i < 8; i++)
                #pragma unroll
                for (int j = 0; j < 8; j++) acc[i][j] += ar[i] * br[j];
        }
        __syncthreads();
    }

    #pragma unroll
    for (int i = 0; i < 8; i++) {
        int row = by * 128 + ty * 8 + i;
        #pragma unroll
        for (int j = 0; j < 8; j++) {
            int col = bx * 128 + tx * 8 + j;
            float v = acc[i][j];
            if (BIAS) v += bias[col];
            if (RES)  v += res[(size_t)row * N + col];
            C[(size_t)row * N + col] = v;
        }
    }
}

// ---------------- RoPE (in place) ----------------
__global__ void rope_kernel(float* __restrict__ t, int nh) {
    int row = blockIdx.x;
    int tid = threadIdx.x;          // nh*64
    int hh = tid >> 6, d = tid & 63;
    int s = row % S_;
    // inv_freq = theta^(-(2d)/128) = exp(-d/64 * ln(1e6))
    float inv = expf(-(float)d * (13.815510557964274f / 64.0f));
    float ang = (float)s * inv;
    float sn, cs; sincosf(ang, &sn, &cs);
    float* p = t + (size_t)row * (nh * DH) + hh * DH + d;
    float x0 = p[0], x1 = p[64];
    p[0]  = x0 * cs - x1 * sn;
    p[64] = x1 * cs + x0 * sn;
}

// ---------------- attention: one block per (b, head, q-row), 128 threads ----------------
__global__ void attn_kernel(const float* __restrict__ q,
                            const float* __restrict__ k,
                            const float* __restrict__ v,
                            const int* __restrict__ mask,
                            float* __restrict__ out) {
    int blk = blockIdx.x;
    int b   = blk / (NH * S_);
    int rem = blk % (NH * S_);
    int h   = rem / S_;
    int qi  = rem % S_;
    int kvh = h / (NH / NKV);
    int tid = threadIdx.x;          // 128

    __shared__ float qs[DH];
    __shared__ float sc[128];
    __shared__ float red[128];

    const float* qrow = q + ((size_t)(b * S_ + qi)) * QD + h * DH;
    qs[tid] = qrow[tid];
    __syncthreads();

    float m = -1e30f, l = 0.f, acc = 0.f;
    const float scale = 0.08838834764831845f;  // 1/sqrt(128)

    for (int kc = 0; kc <= qi; kc += 128) {
        int len = min(128, qi + 1 - kc);
        int j = kc + tid;
        float s = -1e30f;
        bool valid = (tid < len) && (mask[b * S_ + j] > 0);
        if (valid) {
            const float4* kr = (const float4*)(k + ((size_t)(b * S_ + j)) * KVD + kvh * DH);
            const float4* qv = (const float4*)qs;
            float sum = 0.f;
            #pragma unroll
            for (int t = 0; t < 32; t++) {
                float4 a = qv[t]; float4 bb = kr[t];
                sum += a.x * bb.x + a.y * bb.y + a.z * bb.z + a.w * bb.w;
            }
            s = sum * scale;
        }
        red[tid] = s; __syncthreads();
        for (int off = 64; off > 0; off >>= 1) {
            if (tid < off) red[tid] = fmaxf(red[tid], red[tid + off]);
            __syncthreads();
        }
        float cmax = red[0];
        __syncthreads();
        float mnew = fmaxf(m, cmax);
        float p = valid ? expf(s - mnew) : 0.f;
        float alpha = expf(m - mnew);      // first chunk: exp(-1e30 - mnew) = 0
        sc[tid] = p; red[tid] = p; __syncthreads();
        for (int off = 64; off > 0; off >>= 1) {
            if (tid < off) red[tid] += red[tid + off];
            __syncthreads();
        }
        float psum = red[0];
        l = l * alpha + psum;
        m = mnew;
        acc *= alpha;
        const float* vb = v + ((size_t)(b * S_ + kc)) * KVD + kvh * DH + tid;
        for (int jj = 0; jj < len; jj++) acc += sc[jj] * vb[(size_t)jj * KVD];
        __syncthreads();
    }
    out[((size_t)(b * S_ + qi)) * QD + h * DH + tid] = acc / l;
}

// ---------------- silu(gate) * up (in place into gate) ----------------
__global__ void silu_mul_kernel(float* __restrict__ g, const float* __restrict__ u, int n) {
    int i = blockIdx.x * blockDim.x + threadIdx.x;
    if (i < n) {
        float x = g[i];
        float s = x / (1.f + expf(-x));
        g[i] = s * u[i];
    }
}

// ---------------- last_hidden gather ----------------
__global__ void last_kernel(const int* __restrict__ mask,
                            const float* __restrict__ hidden,
                            float* __restrict__ out) {
    int b = blockIdx.x;
    int tid = threadIdx.x;  // 256
    __shared__ int red[256];
    int s = 0;
    for (int i = tid; i < S_; i += 256) s += mask[b * S_ + i];
    red[tid] = s; __syncthreads();
    for (int off = 128; off > 0; off >>= 1) {
        if (tid < off) red[tid] += red[tid + off];
        __syncthreads();
    }
    int pos = red[0] - 1;
    const float* hr = hidden + ((size_t)(b * S_ + pos)) * H_;
    for (int i = tid; i < H_; i += 256) out[(size_t)b * H_ + i] = hr[i];
}

extern "C" void kernel_launch(void* const* d_in, const int* in_sizes, int n_in,
                              void* d_out, int out_size) {
    const int*   ids  = (const int*)d_in[0];
    const int*   mask = (const int*)d_in[1];
    const float* emb  = (const float*)d_in[2];
    const float* wq   = (const float*)d_in[3];
    const float* bq   = (const float*)d_in[4];
    const float* wk   = (const float*)d_in[5];
    const float* bk   = (const float*)d_in[6];
    const float* wv   = (const float*)d_in[7];
    const float* bv   = (const float*)d_in[8];
    const float* wo   = (const float*)d_in[9];
    const float* wg   = (const float*)d_in[10];
    const float* wu   = (const float*)d_in[11];
    const float* wd   = (const float*)d_in[12];
    const float* ln1  = (const float*)d_in[13];
    const float* ln2  = (const float*)d_in[14];
    const float* lnf  = (const float*)d_in[15];
    float* out = (float*)d_out;

    float *x, *h, *q, *k, *v, *att, *gate, *up;
    cudaGetSymbolAddress((void**)&x,    g_x);
    cudaGetSymbolAddress((void**)&h,    g_h);
    cudaGetSymbolAddress((void**)&q,    g_q);
    cudaGetSymbolAddress((void**)&k,    g_k);
    cudaGetSymbolAddress((void**)&v,    g_v);
    cudaGetSymbolAddress((void**)&att,  g_att);
    cudaGetSymbolAddress((void**)&gate, g_gate);
    cudaGetSymbolAddress((void**)&up,   g_up);

    embed_kernel<<<ROWS, 256>>>(ids, emb, x);

    for (int l = 0; l < L_; l++) {
        rmsnorm_kernel<<<ROWS, 256>>>(x, ln1 + (size_t)l * H_, h);

        sgemm_kernel<true, false><<<dim3(QD / 128, ROWS / 128), 256>>>(
            ROWS, QD, H_, h, wq + (size_t)l * H_ * QD, bq + (size_t)l * QD, nullptr, q);
        sgemm_kernel<true, false><<<dim3(KVD / 128, ROWS / 128), 256>>>(
            ROWS, KVD, H_, h, wk + (size_t)l * H_ * KVD, bk + (size_t)l * KVD, nullptr, k);
        sgemm_kernel<true, false><<<dim3(KVD / 128, ROWS / 128), 256>>>(
            ROWS, KVD, H_, h, wv + (size_t)l * H_ * KVD, bv + (size_t)l * KVD, nullptr, v);

        rope_kernel<<<ROWS, NH * 64>>>(q, NH);
        rope_kernel<<<ROWS, NKV * 64>>>(k, NKV);

        attn_kernel<<<B_ * NH * S_, 128>>>(q, k, v, mask, att);

        sgemm_kernel<false, true><<<dim3(H_ / 128, ROWS / 128), 256>>>(
            ROWS, H_, QD, att, wo + (size_t)l * QD * H_, nullptr, x, x);

        rmsnorm_kernel<<<ROWS, 256>>>(x, ln2 + (size_t)l * H_, h);

        sgemm_kernel<false, false><<<dim3(F_ / 128, ROWS / 128), 256>>>(
            ROWS, F_, H_, h, wg + (size_t)l * H_ * F_, nullptr, nullptr, gate);
        sgemm_kernel<false, false><<<dim3(F_ / 128, ROWS / 128), 256>>>(
            ROWS, F_, H_, h, wu + (size_t)l * H_ * F_, nullptr, nullptr, up);

        silu_mul_kernel<<<((size_t)ROWS * F_ + 255) / 256, 256>>>(gate, up, ROWS * F_);

        sgemm_kernel<false, true><<<dim3(H_ / 128, ROWS / 128), 256>>>(
            ROWS, H_, F_, gate, wd + (size_t)l * F_ * H_, nullptr, x, x);
    }

    rmsnorm_kernel<<<ROWS, 256>>>(x, lnf, out);
    last_kernel<<<B_, 256>>>(mask, out, out + (size_t)ROWS * H_);
}

// round 3
// speedup vs baseline: 1.2061x; 1.2061x over previous
#include <cuda_runtime.h>
#include <math.h>
#include <stdint.h>

// Problem constants (fixed by setup_inputs)
#define B_    2
#define S_    1024
#define ROWS  (B_*S_)       // 2048
#define H_    1536
#define F_    8960
#define L_    2
#define NH    12
#define NKV   2
#define DH    128
#define QD    (NH*DH)       // 1536
#define KVD   (NKV*DH)      // 256
#define EPS_  1e-6f

// Scratch (device globals: no allocation allowed)
__device__ float g_x  [ROWS*H_];
__device__ float g_h  [ROWS*H_];
__device__ float g_q  [ROWS*QD];
__device__ float g_k  [ROWS*KVD];
__device__ float g_v  [ROWS*KVD];
__device__ float g_att[ROWS*QD];
__device__ float g_gate[(size_t)ROWS*F_];
__device__ float g_up  [(size_t)ROWS*F_];

// ---------------- embedding gather ----------------
__global__ void embed_kernel(const int* __restrict__ ids,
                             const float* __restrict__ emb,
                             float* __restrict__ x) {
    int row = blockIdx.x;
    int id  = ids[row];
    const float* e = emb + (size_t)id * H_;
    float* xr = x + (size_t)row * H_;
    for (int i = threadIdx.x; i < H_; i += blockDim.x) xr[i] = e[i];
}

// ---------------- rmsnorm ----------------
__global__ void rmsnorm_kernel(const float* __restrict__ x,
                               const float* __restrict__ w,
                               float* __restrict__ out) {
    int row = blockIdx.x;
    const float* xr = x + (size_t)row * H_;
    int tid = threadIdx.x;            // 256
    float s = 0.f;
    for (int i = tid; i < H_; i += 256) { float v = xr[i]; s += v * v; }
    __shared__ float red[256];
    red[tid] = s; __syncthreads();
    for (int off = 128; off > 0; off >>= 1) {
        if (tid < off) red[tid] += red[tid + off];
        __syncthreads();
    }
    float rs = rsqrtf(red[0] / (float)H_ + EPS_);
    float* o = out + (size_t)row * H_;
    for (int i = tid; i < H_; i += 256) o[i] = xr[i] * rs * w[i];
}

// ---------------- TF32 helpers ----------------
__device__ __forceinline__ void split_tf32(float x, uint32_t& hi, uint32_t& lo) {
    asm("cvt.rna.tf32.f32 %0, %1;" : "=r"(hi) : "f"(x));
    float r = x - __uint_as_float(hi);
    asm("cvt.rna.tf32.f32 %0, %1;" : "=r"(lo) : "f"(r));
}

__device__ __forceinline__ void mma_tf32(float c[4], const uint32_t a[4], const uint32_t b[2]) {
    asm volatile(
        "mma.sync.aligned.m16n8k8.row.col.f32.tf32.tf32.f32 "
        "{%0,%1,%2,%3}, {%4,%5,%6,%7}, {%8,%9}, {%0,%1,%2,%3};"
        : "+f"(c[0]), "+f"(c[1]), "+f"(c[2]), "+f"(c[3])
        : "r"(a[0]), "r"(a[1]), "r"(a[2]), "r"(a[3]), "r"(b[0]), "r"(b[1]));
}

__device__ __forceinline__ void cp16(float* s, const float* g) {
    uint32_t sa = (uint32_t)__cvta_generic_to_shared(s);
    asm volatile("cp.async.cg.shared.global [%0], [%1], 16;" :: "r"(sa), "l"(g));
}

// ---------------- 3xTF32 tensor-core GEMM ----------------
// C[M,N] = A[M,K] @ B[K,N] (+bias) (+res). BM=BN=128, BK=32, 2-stage cp.async.
// 256 threads = 8 warps, each warp computes 64x32 via 4x4 m16n8k8 tiles.
// Each input split hi/lo in tf32; accumulate hi*hi + lo*hi + hi*lo (fp32-level accuracy).
// Requires M%128==0, N%128==0, K%32==0.
#define ASTRIDE 36
#define BSTRIDE 136
#define A_TILE (128 * ASTRIDE)
#define B_TILE (32 * BSTRIDE)
#define SMEM_BYTES ((2 * A_TILE + 2 * B_TILE) * 4)

template<bool BIAS, bool RES>
__global__ void __launch_bounds__(256, 1)
mma_gemm(int M, int N, int K,
         const float* __restrict__ A, const float* __restrict__ Bm,
         const float* __restrict__ bias, const float* __restrict__ res,
         float* __restrict__ C) {
    extern __shared__ float smem[];
    float* Asb[2] = { smem, smem + A_TILE };
    float* Bsb[2] = { smem + 2 * A_TILE, smem + 2 * A_TILE + B_TILE };

    const int tid  = threadIdx.x;
    const int lane = tid & 31;
    const int wid  = tid >> 5;
    const int wm   = wid & 1;    // 0..1 : 64-row slab
    const int wn   = wid >> 1;   // 0..3 : 32-col slab
    const int bx = blockIdx.x, by = blockIdx.y;

    const int a_row = tid >> 3;          // 0..31 (+ i*32)
    const int a_col = (tid & 7) * 4;     // 0..28
    const int b_row = tid >> 5;          // 0..7 (+ i*8)
    const int b_col = (tid & 31) * 4;    // 0..124
    const float* Ag = A + (size_t)(by * 128 + a_row) * K + a_col;
    const float* Bg = Bm + (size_t)b_row * N + bx * 128 + b_col;

    float acc[4][4][4];
    #pragma unroll
    for (int m = 0; m < 4; m++)
        #pragma unroll
        for (int n = 0; n < 4; n++)
            #pragma unroll
            for (int r = 0; r < 4; r++) acc[m][n][r] = 0.f;

    const int NT = K / 32;

    // prologue: stage 0
    {
        #pragma unroll
        for (int i = 0; i < 4; i++)
            cp16(Asb[0] + (a_row + i * 32) * ASTRIDE + a_col, Ag + (size_t)(i * 32) * K);
        #pragma unroll
        for (int i = 0; i < 4; i++)
            cp16(Bsb[0] + (b_row + i * 8) * BSTRIDE + b_col, Bg + (size_t)(i * 8) * N);
        asm volatile("cp.async.commit_group;");
    }

    const int fr = lane >> 2;   // 0..7
    const int fc = lane & 3;    // 0..3

    for (int t = 0; t < NT; t++) {
        if (t + 1 < NT) {
            const float* Agt = Ag + (t + 1) * 32;
            const float* Bgt = Bg + (size_t)(t + 1) * 32 * N;
            float* As1 = Asb[(t + 1) & 1];
            float* Bs1 = Bsb[(t + 1) & 1];
            #pragma unroll
            for (int i = 0; i < 4; i++)
                cp16(As1 + (a_row + i * 32) * ASTRIDE + a_col, Agt + (size_t)(i * 32) * K);
            #pragma unroll
            for (int i = 0; i < 4; i++)
                cp16(Bs1 + (b_row + i * 8) * BSTRIDE + b_col, Bgt + (size_t)(i * 8) * N);
            asm volatile("cp.async.commit_group;");
            asm volatile("cp.async.wait_group 1;");
        } else {
            asm volatile("cp.async.wait_group 0;");
        }
        __syncthreads();

        const float* As = Asb[t & 1];
        const float* Bs = Bsb[t & 1];

        #pragma unroll
        for (int ks = 0; ks < 4; ks++) {
            const int k0 = ks * 8;
            uint32_t ah[4][4], al[4][4], bh[4][2], bl[4][2];
            #pragma unroll
            for (int m = 0; m < 4; m++) {
                const float* ap = As + (wm * 64 + m * 16 + fr) * ASTRIDE + k0 + fc;
                split_tf32(ap[0],               ah[m][0], al[m][0]);
                split_tf32(ap[8 * ASTRIDE],     ah[m][1], al[m][1]);
                split_tf32(ap[4],               ah[m][2], al[m][2]);
                split_tf32(ap[8 * ASTRIDE + 4], ah[m][3], al[m][3]);
            }
            #pragma unroll
            for (int n = 0; n < 4; n++) {
                const float* bp = Bs + (k0 + fc) * BSTRIDE + wn * 32 + n * 8 + fr;
                split_tf32(bp[0],           bh[n][0], bl[n][0]);
                split_tf32(bp[4 * BSTRIDE], bh[n][1], bl[n][1]);
            }
            #pragma unroll
            for (int m = 0; m < 4; m++)
                #pragma unroll
                for (int n = 0; n < 4; n++) {
                    mma_tf32(acc[m][n], ah[m], bh[n]);
                    mma_tf32(acc[m][n], al[m], bh[n]);
                    mma_tf32(acc[m][n], ah[m], bl[n]);
                }
        }
        __syncthreads();
    }

    // epilogue
    const int fc2 = (lane & 3) * 2;
    #pragma unroll
    for (int m = 0; m < 4; m++) {
        int row0 = by * 128 + wm * 64 + m * 16 + fr;
        #pragma unroll
        for (int n = 0; n < 4; n++) {
            int col = bx * 128 + wn * 32 + n * 8 + fc2;
            float v0 = acc[m][n][0], v1 = acc[m][n][1];
            float v2 = acc[m][n][2], v3 = acc[m][n][3];
            if (BIAS) {
                float b0 = bias[col], b1 = bias[col + 1];
                v0 += b0; v1 += b1; v2 += b0; v3 += b1;
            }
            if (RES) {
                v0 += res[(size_t)row0 * N + col];
                v1 += res[(size_t)row0 * N + col + 1];
                v2 += res[(size_t)(row0 + 8) * N + col];
                v3 += res[(size_t)(row0 + 8) * N + col + 1];
            }
            C[(size_t)row0 * N + col]           = v0;
            C[(size_t)row0 * N + col + 1]       = v1;
            C[(size_t)(row0 + 8) * N + col]     = v2;
            C[(size_t)(row0 + 8) * N + col + 1] = v3;
        }
    }
}

// ---------------- RoPE (in place) ----------------
__global__ void rope_kernel(float* __restrict__ t, int nh) {
    int row = blockIdx.x;
    int tid = threadIdx.x;          // nh*64
    int hh = tid >> 6, d = tid & 63;
    int s = row % S_;
    float inv = expf(-(float)d * (13.815510557964274f / 64.0f));
    float ang = (float)s * inv;
    float sn, cs; sincosf(ang, &sn, &cs);
    float* p = t + (size_t)row * (nh * DH) + hh * DH + d;
    float x0 = p[0], x1 = p[64];
    p[0]  = x0 * cs - x1 * sn;
    p[64] = x1 * cs + x0 * sn;
}

// ---------------- attention: one block per (b, head, q-row), 128 threads ----------------
__global__ void attn_kernel(const float* __restrict__ q,
                            const float* __restrict__ k,
                            const float* __restrict__ v,
                            const int* __restrict__ mask,
                            float* __restrict__ out) {
    int blk = blockIdx.x;
    int b   = blk / (NH * S_);
    int rem = blk % (NH * S_);
    int h   = rem / S_;
    int qi  = rem % S_;
    int kvh = h / (NH / NKV);
    int tid = threadIdx.x;          // 128

    __shared__ float qs[DH];
    __shared__ float sc[128];
    __shared__ float red[128];

    const float* qrow = q + ((size_t)(b * S_ + qi)) * QD + h * DH;
    qs[tid] = qrow[tid];
    __syncthreads();

    float m = -1e30f, l = 0.f, acc = 0.f;
    const float scale = 0.08838834764831845f;  // 1/sqrt(128)

    for (int kc = 0; kc <= qi; kc += 128) {
        int len = min(128, qi + 1 - kc);
        int j = kc + tid;
        float s = -1e30f;
        bool valid = (tid < len) && (mask[b * S_ + j] > 0);
        if (valid) {
            const float4* kr = (const float4*)(k + ((size_t)(b * S_ + j)) * KVD + kvh * DH);
            const float4* qv = (const float4*)qs;
            float sum = 0.f;
            #pragma unroll
            for (int t = 0; t < 32; t++) {
                float4 a = qv[t]; float4 bb = kr[t];
                sum += a.x * bb.x + a.y * bb.y + a.z * bb.z + a.w * bb.w;
            }
            s = sum * scale;
        }
        red[tid] = s; __syncthreads();
        for (int off = 64; off > 0; off >>= 1) {
            if (tid < off) red[tid] = fmaxf(red[tid], red[tid + off]);
            __syncthreads();
        }
        float cmax = red[0];
        __syncthreads();
        float mnew = fmaxf(m, cmax);
        float p = valid ? expf(s - mnew) : 0.f;
        float alpha = expf(m - mnew);
        sc[tid] = p; red[tid] = p; __syncthreads();
        for (int off = 64; off > 0; off >>= 1) {
            if (tid < off) red[tid] += red[tid + off];
            __syncthreads();
        }
        float psum = red[0];
        l = l * alpha + psum;
        m = mnew;
        acc *= alpha;
        const float* vb = v + ((size_t)(b * S_ + kc)) * KVD + kvh * DH + tid;
        for (int jj = 0; jj < len; jj++) acc += sc[jj] * vb[(size_t)jj * KVD];
        __syncthreads();
    }
    out[((size_t)(b * S_ + qi)) * QD + h * DH + tid] = acc / l;
}

// ---------------- silu(gate) * up (in place into gate) ----------------
__global__ void silu_mul_kernel(float* __restrict__ g, const float* __restrict__ u, int n) {
    int i = blockIdx.x * blockDim.x + threadIdx.x;
    if (i < n) {
        float x = g[i];
        float s = x / (1.f + expf(-x));
        g[i] = s * u[i];
    }
}

// ---------------- last_hidden gather ----------------
__global__ void last_kernel(const int* __restrict__ mask,
                            const float* __restrict__ hidden,
                            float* __restrict__ out) {
    int b = blockIdx.x;
    int tid = threadIdx.x;  // 256
    __shared__ int red[256];
    int s = 0;
    for (int i = tid; i < S_; i += 256) s += mask[b * S_ + i];
    red[tid] = s; __syncthreads();
    for (int off = 128; off > 0; off >>= 1) {
        if (tid < off) red[tid] += red[tid + off];
        __syncthreads();
    }
    int pos = red[0] - 1;
    const float* hr = hidden + ((size_t)(b * S_ + pos)) * H_;
    for (int i = tid; i < H_; i += 256) out[(size_t)b * H_ + i] = hr[i];
}

extern "C" void kernel_launch(void* const* d_in, const int* in_sizes, int n_in,
                              void* d_out, int out_size) {
    const int*   ids  = (const int*)d_in[0];
    const int*   mask = (const int*)d_in[1];
    const float* emb  = (const float*)d_in[2];
    const float* wq   = (const float*)d_in[3];
    const float* bq   = (const float*)d_in[4];
    const float* wk   = (const float*)d_in[5];
    const float* bk   = (const float*)d_in[6];
    const float* wv   = (const float*)d_in[7];
    const float* bv   = (const float*)d_in[8];
    const float* wo   = (const float*)d_in[9];
    const float* wg   = (const float*)d_in[10];
    const float* wu   = (const float*)d_in[11];
    const float* wd   = (const float*)d_in[12];
    const float* ln1  = (const float*)d_in[13];
    const float* ln2  = (const float*)d_in[14];
    const float* lnf  = (const float*)d_in[15];
    float* out = (float*)d_out;

    float *x, *h, *q, *k, *v, *att, *gate, *up;
    cudaGetSymbolAddress((void**)&x,    g_x);
    cudaGetSymbolAddress((void**)&h,    g_h);
    cudaGetSymbolAddress((void**)&q,    g_q);
    cudaGetSymbolAddress((void**)&k,    g_k);
    cudaGetSymbolAddress((void**)&v,    g_v);
    cudaGetSymbolAddress((void**)&att,  g_att);
    cudaGetSymbolAddress((void**)&gate, g_gate);
    cudaGetSymbolAddress((void**)&up,   g_up);

    static bool attr_set = false;
    if (!attr_set) {
        cudaFuncSetAttribute(mma_gemm<true, false>,
                             cudaFuncAttributeMaxDynamicSharedMemorySize, SMEM_BYTES);
        cudaFuncSetAttribute(mma_gemm<false, true>,
                             cudaFuncAttributeMaxDynamicSharedMemorySize, SMEM_BYTES);
        cudaFuncSetAttribute(mma_gemm<false, false>,
                             cudaFuncAttributeMaxDynamicSharedMemorySize, SMEM_BYTES);
        attr_set = true;
    }

    embed_kernel<<<ROWS, 256>>>(ids, emb, x);

    for (int l = 0; l < L_; l++) {
        rmsnorm_kernel<<<ROWS, 256>>>(x, ln1 + (size_t)l * H_, h);

        mma_gemm<true, false><<<dim3(QD / 128, ROWS / 128), 256, SMEM_BYTES>>>(
            ROWS, QD, H_, h, wq + (size_t)l * H_ * QD, bq + (size_t)l * QD, nullptr, q);
        mma_gemm<true, false><<<dim3(KVD / 128, ROWS / 128), 256, SMEM_BYTES>>>(
            ROWS, KVD, H_, h, wk + (size_t)l * H_ * KVD, bk + (size_t)l * KVD, nullptr, k);
        mma_gemm<true, false><<<dim3(KVD / 128, ROWS / 128), 256, SMEM_BYTES>>>(
            ROWS, KVD, H_, h, wv + (size_t)l * H_ * KVD, bv + (size_t)l * KVD, nullptr, v);

        rope_kernel<<<ROWS, NH * 64>>>(q, NH);
        rope_kernel<<<ROWS, NKV * 64>>>(k, NKV);

        attn_kernel<<<B_ * NH * S_, 128>>>(q, k, v, mask, att);

        mma_gemm<false, true><<<dim3(H_ / 128, ROWS / 128), 256, SMEM_BYTES>>>(
            ROWS, H_, QD, att, wo + (size_t)l * QD * H_, nullptr, x, x);

        rmsnorm_kernel<<<ROWS, 256>>>(x, ln2 + (size_t)l * H_, h);

        mma_gemm<false, false><<<dim3(F_ / 128, ROWS / 128), 256, SMEM_BYTES>>>(
            ROWS, F_, H_, h, wg + (size_t)l * H_ * F_, nullptr, nullptr, gate);
        mma_gemm<false, false><<<dim3(F_ / 128, ROWS / 128), 256, SMEM_BYTES>>>(
            ROWS, F_, H_, h, wu + (size_t)l * H_ * F_, nullptr, nullptr, up);

        silu_mul_kernel<<<((size_t)ROWS * F_ + 255) / 256, 256>>>(gate, up, ROWS * F_);

        mma_gemm<false, true><<<dim3(H_ / 128, ROWS / 128), 256, SMEM_BYTES>>>(
            ROWS, H_, F_, gate, wd + (size_t)l * F_ * H_, nullptr, x, x);
    }

    rmsnorm_kernel<<<ROWS, 256>>>(x, lnf, out);
    last_kernel<<<B_, 256>>>(mask, out, out + (size_t)ROWS * H_);
}

// round 4
// speedup vs baseline: 1.2410x; 1.0290x over previous
#include <cuda_runtime.h>
#include <math.h>
#include <stdint.h>

// Problem constants (fixed by setup_inputs)
#define B_    2
#define S_    1024
#define ROWS  (B_*S_)       // 2048
#define H_    1536
#define F_    8960
#define L_    2
#define NH    12
#define NKV   2
#define DH    128
#define QD    (NH*DH)       // 1536
#define KVD   (NKV*DH)      // 256
#define EPS_  1e-6f

// Scratch (device globals: no allocation allowed)
__device__ float g_x  [ROWS*H_];
__device__ float g_h  [ROWS*H_];
__device__ float g_q  [ROWS*QD];
__device__ float g_k  [ROWS*KVD];
__device__ float g_v  [ROWS*KVD];
__device__ float g_att[ROWS*QD];
__device__ float g_gate[(size_t)ROWS*F_];
__device__ float g_up  [(size_t)ROWS*F_];

// ---------------- embedding gather ----------------
__global__ void embed_kernel(const int* __restrict__ ids,
                             const float* __restrict__ emb,
                             float* __restrict__ x) {
    int row = blockIdx.x;
    int id  = ids[row];
    const float* e = emb + (size_t)id * H_;
    float* xr = x + (size_t)row * H_;
    for (int i = threadIdx.x; i < H_; i += blockDim.x) xr[i] = e[i];
}

// ---------------- rmsnorm ----------------
__global__ void rmsnorm_kernel(const float* __restrict__ x,
                               const float* __restrict__ w,
                               float* __restrict__ out) {
    int row = blockIdx.x;
    const float* xr = x + (size_t)row * H_;
    int tid = threadIdx.x;            // 256
    float s = 0.f;
    for (int i = tid; i < H_; i += 256) { float v = xr[i]; s += v * v; }
    __shared__ float red[256];
    red[tid] = s; __syncthreads();
    for (int off = 128; off > 0; off >>= 1) {
        if (tid < off) red[tid] += red[tid + off];
        __syncthreads();
    }
    float rs = rsqrtf(red[0] / (float)H_ + EPS_);
    float* o = out + (size_t)row * H_;
    for (int i = tid; i < H_; i += 256) o[i] = xr[i] * rs * w[i];
}

// ---------------- TF32 helpers ----------------
__device__ __forceinline__ void split_tf32(float x, uint32_t& hi, uint32_t& lo) {
    asm("cvt.rna.tf32.f32 %0, %1;" : "=r"(hi) : "f"(x));
    float r = x - __uint_as_float(hi);
    asm("cvt.rna.tf32.f32 %0, %1;" : "=r"(lo) : "f"(r));
}

__device__ __forceinline__ void mma_tf32(float c[4], const uint32_t a[4], const uint32_t b[2]) {
    asm volatile(
        "mma.sync.aligned.m16n8k8.row.col.f32.tf32.tf32.f32 "
        "{%0,%1,%2,%3}, {%4,%5,%6,%7}, {%8,%9}, {%0,%1,%2,%3};"
        : "+f"(c[0]), "+f"(c[1]), "+f"(c[2]), "+f"(c[3])
        : "r"(a[0]), "r"(a[1]), "r"(a[2]), "r"(a[3]), "r"(b[0]), "r"(b[1]));
}

__device__ __forceinline__ void cp16(float* s, const float* g) {
    uint32_t sa = (uint32_t)__cvta_generic_to_shared(s);
    asm volatile("cp.async.cg.shared.global [%0], [%1], 16;" :: "r"(sa), "l"(g));
}

// ---------------- 3xTF32 GEMM body: 512 threads, BM=BN=128, BK=32 ----------------
// 16 warps in 4x4 grid, each computes a 32x32 warp tile (acc 2x4 m16n8 frags).
// 2-stage cp.async double buffering. Requires K%32==0.
#define ASTRIDE 36
#define BSTRIDE 136
#define A_TILE (128 * ASTRIDE)
#define B_TILE (32 * BSTRIDE)
#define SMEM_BYTES ((2 * A_TILE + 2 * B_TILE) * 4)

template<bool BIAS, bool RES>
__device__ __forceinline__ void
gemm_body(int K, int lda, int ldb, int ldc,
          const float* __restrict__ Ag0,   // A + rowblock*lda
          const float* __restrict__ Bg0,   // B + colblock       (row stride ldb)
          const float* __restrict__ bias,  // bias + colblock
          const float* __restrict__ res,   // res + rowblock*ldc + colblock
          float* __restrict__ C,           // C   + rowblock*ldc + colblock
          float* smem) {
    float* Asb[2] = { smem, smem + A_TILE };
    float* Bsb[2] = { smem + 2 * A_TILE, smem + 2 * A_TILE + B_TILE };

    const int tid  = threadIdx.x;
    const int lane = tid & 31;
    const int wid  = tid >> 5;
    const int wm   = wid & 3;    // 0..3 : 32-row slab
    const int wn   = wid >> 2;   // 0..3 : 32-col slab

    const int a_row = tid >> 3;          // 0..63 (+64)
    const int a_col = (tid & 7) * 4;
    const int b_row = tid >> 5;          // 0..15 (+16)
    const int b_col = (tid & 31) * 4;
    const float* Ag = Ag0 + (size_t)a_row * lda + a_col;
    const float* Bg = Bg0 + (size_t)b_row * ldb + b_col;

    float acc[2][4][4];
    #pragma unroll
    for (int m = 0; m < 2; m++)
        #pragma unroll
        for (int n = 0; n < 4; n++)
            #pragma unroll
            for (int r = 0; r < 4; r++) acc[m][n][r] = 0.f;

    const int NT = K / 32;

    // prologue
    #pragma unroll
    for (int i = 0; i < 2; i++)
        cp16(Asb[0] + (a_row + i * 64) * ASTRIDE + a_col, Ag + (size_t)(i * 64) * lda);
    #pragma unroll
    for (int i = 0; i < 2; i++)
        cp16(Bsb[0] + (b_row + i * 16) * BSTRIDE + b_col, Bg + (size_t)(i * 16) * ldb);
    asm volatile("cp.async.commit_group;");

    const int fr = lane >> 2;   // 0..7
    const int fc = lane & 3;    // 0..3

    for (int t = 0; t < NT; t++) {
        if (t + 1 < NT) {
            const float* Agt = Ag + (t + 1) * 32;
            const float* Bgt = Bg + (size_t)(t + 1) * 32 * ldb;
            float* As1 = Asb[(t + 1) & 1];
            float* Bs1 = Bsb[(t + 1) & 1];
            #pragma unroll
            for (int i = 0; i < 2; i++)
                cp16(As1 + (a_row + i * 64) * ASTRIDE + a_col, Agt + (size_t)(i * 64) * lda);
            #pragma unroll
            for (int i = 0; i < 2; i++)
                cp16(Bs1 + (b_row + i * 16) * BSTRIDE + b_col, Bgt + (size_t)(i * 16) * ldb);
            asm volatile("cp.async.commit_group;");
            asm volatile("cp.async.wait_group 1;");
        } else {
            asm volatile("cp.async.wait_group 0;");
        }
        __syncthreads();

        const float* As = Asb[t & 1];
        const float* Bs = Bsb[t & 1];

        #pragma unroll
        for (int ks = 0; ks < 4; ks++) {
            const int k0 = ks * 8;
            uint32_t ah[2][4], al[2][4], bh[4][2], bl[4][2];
            #pragma unroll
            for (int m = 0; m < 2; m++) {
                const float* ap = As + (wm * 32 + m * 16 + fr) * ASTRIDE + k0 + fc;
                split_tf32(ap[0],               ah[m][0], al[m][0]);
                split_tf32(ap[8 * ASTRIDE],     ah[m][1], al[m][1]);
                split_tf32(ap[4],               ah[m][2], al[m][2]);
                split_tf32(ap[8 * ASTRIDE + 4], ah[m][3], al[m][3]);
            }
            #pragma unroll
            for (int n = 0; n < 4; n++) {
                const float* bp = Bs + (k0 + fc) * BSTRIDE + wn * 32 + n * 8 + fr;
                split_tf32(bp[0],           bh[n][0], bl[n][0]);
                split_tf32(bp[4 * BSTRIDE], bh[n][1], bl[n][1]);
            }
            #pragma unroll
            for (int m = 0; m < 2; m++)
                #pragma unroll
                for (int n = 0; n < 4; n++) {
                    mma_tf32(acc[m][n], ah[m], bh[n]);
                    mma_tf32(acc[m][n], al[m], bh[n]);
                    mma_tf32(acc[m][n], ah[m], bl[n]);
                }
        }
        __syncthreads();
    }

    // epilogue
    const int fc2 = (lane & 3) * 2;
    #pragma unroll
    for (int m = 0; m < 2; m++) {
        int row0 = wm * 32 + m * 16 + fr;
        #pragma unroll
        for (int n = 0; n < 4; n++) {
            int col = wn * 32 + n * 8 + fc2;
            float v0 = acc[m][n][0], v1 = acc[m][n][1];
            float v2 = acc[m][n][2], v3 = acc[m][n][3];
            if (BIAS) {
                float b0 = bias[col], b1 = bias[col + 1];
                v0 += b0; v1 += b1; v2 += b0; v3 += b1;
            }
            if (RES) {
                v0 += res[(size_t)row0 * ldc + col];
                v1 += res[(size_t)row0 * ldc + col + 1];
                v2 += res[(size_t)(row0 + 8) * ldc + col];
                v3 += res[(size_t)(row0 + 8) * ldc + col + 1];
            }
            C[(size_t)row0 * ldc + col]           = v0;
            C[(size_t)row0 * ldc + col + 1]       = v1;
            C[(size_t)(row0 + 8) * ldc + col]     = v2;
            C[(size_t)(row0 + 8) * ldc + col + 1] = v3;
        }
    }
}

// generic GEMM (used for o-proj and down-proj, both with residual)
__global__ void __launch_bounds__(512, 1)
mma_gemm_res(int K, int N,
             const float* __restrict__ A, const float* __restrict__ Bm,
             const float* __restrict__ res, float* __restrict__ C) {
    extern __shared__ float smem[];
    const int bx = blockIdx.x, by = blockIdx.y;
    gemm_body<false, true>(K, K, N, N,
                           A + (size_t)by * 128 * K,
                           Bm + bx * 128,
                           nullptr,
                           res + (size_t)by * 128 * N + bx * 128,
                           C + (size_t)by * 128 * N + bx * 128,
                           smem);
}

// fused QKV projection: grid.x = 16 (12 q blocks, 2 k, 2 v)
__global__ void __launch_bounds__(512, 1)
qkv_kernel(const float* __restrict__ A,
           const float* __restrict__ wq, const float* __restrict__ bq,
           const float* __restrict__ wk, const float* __restrict__ bk,
           const float* __restrict__ wv, const float* __restrict__ bv,
           float* __restrict__ q, float* __restrict__ k, float* __restrict__ v) {
    extern __shared__ float smem[];
    const int bx = blockIdx.x, by = blockIdx.y;
    const float *Bp, *bp; float* Cp; int ld, cb;
    if (bx < 12)      { cb = bx * 128;        Bp = wq; bp = bq; Cp = q; ld = QD;  }
    else if (bx < 14) { cb = (bx - 12) * 128; Bp = wk; bp = bk; Cp = k; ld = KVD; }
    else              { cb = (bx - 14) * 128; Bp = wv; bp = bv; Cp = v; ld = KVD; }
    gemm_body<true, false>(H_, H_, ld, ld,
                           A + (size_t)by * 128 * H_,
                           Bp + cb, bp + cb, nullptr,
                           Cp + (size_t)by * 128 * ld + cb,
                           smem);
}

// fused gate+up projection: grid.x = 140 (70 gate blocks, 70 up)
__global__ void __launch_bounds__(512, 1)
gateup_kernel(const float* __restrict__ A,
              const float* __restrict__ wg, const float* __restrict__ wu,
              float* __restrict__ gate, float* __restrict__ up) {
    extern __shared__ float smem[];
    const int bx = blockIdx.x, by = blockIdx.y;
    const float* Bp; float* Cp; int cb;
    if (bx < 70) { cb = bx * 128;        Bp = wg; Cp = gate; }
    else         { cb = (bx - 70) * 128; Bp = wu; Cp = up;   }
    gemm_body<false, false>(H_, H_, F_, F_,
                            A + (size_t)by * 128 * H_,
                            Bp + cb, nullptr, nullptr,
                            Cp + (size_t)by * 128 * F_ + cb,
                            smem);
}

// ---------------- RoPE (in place) ----------------
__global__ void rope_kernel(float* __restrict__ t, int nh) {
    int row = blockIdx.x;
    int tid = threadIdx.x;          // nh*64
    int hh = tid >> 6, d = tid & 63;
    int s = row % S_;
    float inv = expf(-(float)d * (13.815510557964274f / 64.0f));
    float ang = (float)s * inv;
    float sn, cs; sincosf(ang, &sn, &cs);
    float* p = t + (size_t)row * (nh * DH) + hh * DH + d;
    float x0 = p[0], x1 = p[64];
    p[0]  = x0 * cs - x1 * sn;
    p[64] = x1 * cs + x0 * sn;
}

// ---------------- attention: one block per (b, head, q-row), 128 threads ----------------
__global__ void attn_kernel(const float* __restrict__ q,
                            const float* __restrict__ k,
                            const float* __restrict__ v,
                            const int* __restrict__ mask,
                            float* __restrict__ out) {
    int blk = blockIdx.x;
    int b   = blk / (NH * S_);
    int rem = blk % (NH * S_);
    int h   = rem / S_;
    int qi  = rem % S_;
    int kvh = h / (NH / NKV);
    int tid = threadIdx.x;          // 128

    __shared__ float qs[DH];
    __shared__ float sc[128];
    __shared__ float red[128];

    const float* qrow = q + ((size_t)(b * S_ + qi)) * QD + h * DH;
    qs[tid] = qrow[tid];
    __syncthreads();

    float m = -1e30f, l = 0.f, acc = 0.f;
    const float scale = 0.08838834764831845f;  // 1/sqrt(128)

    for (int kc = 0; kc <= qi; kc += 128) {
        int len = min(128, qi + 1 - kc);
        int j = kc + tid;
        float s = -1e30f;
        bool valid = (tid < len) && (mask[b * S_ + j] > 0);
        if (valid) {
            const float4* kr = (const float4*)(k + ((size_t)(b * S_ + j)) * KVD + kvh * DH);
            const float4* qv = (const float4*)qs;
            float sum = 0.f;
            #pragma unroll
            for (int t = 0; t < 32; t++) {
                float4 a = qv[t]; float4 bb = kr[t];
                sum += a.x * bb.x + a.y * bb.y + a.z * bb.z + a.w * bb.w;
            }
            s = sum * scale;
        }
        red[tid] = s; __syncthreads();
        for (int off = 64; off > 0; off >>= 1) {
            if (tid < off) red[tid] = fmaxf(red[tid], red[tid + off]);
            __syncthreads();
        }
        float cmax = red[0];
        __syncthreads();
        float mnew = fmaxf(m, cmax);
        float p = valid ? expf(s - mnew) : 0.f;
        float alpha = expf(m - mnew);
        sc[tid] = p; red[tid] = p; __syncthreads();
        for (int off = 64; off > 0; off >>= 1) {
            if (tid < off) red[tid] += red[tid + off];
            __syncthreads();
        }
        float psum = red[0];
        l = l * alpha + psum;
        m = mnew;
        acc *= alpha;
        const float* vb = v + ((size_t)(b * S_ + kc)) * KVD + kvh * DH + tid;
        for (int jj = 0; jj < len; jj++) acc += sc[jj] * vb[(size_t)jj * KVD];
        __syncthreads();
    }
    out[((size_t)(b * S_ + qi)) * QD + h * DH + tid] = acc / l;
}

// ---------------- silu(gate) * up (in place into gate) ----------------
__global__ void silu_mul_kernel(float* __restrict__ g, const float* __restrict__ u, int n) {
    int i = blockIdx.x * blockDim.x + threadIdx.x;
    if (i < n) {
        float x = g[i];
        float s = x / (1.f + expf(-x));
        g[i] = s * u[i];
    }
}

// ---------------- last_hidden gather ----------------
__global__ void last_kernel(const int* __restrict__ mask,
                            const float* __restrict__ hidden,
                            float* __restrict__ out) {
    int b = blockIdx.x;
    int tid = threadIdx.x;  // 256
    __shared__ int red[256];
    int s = 0;
    for (int i = tid; i < S_; i += 256) s += mask[b * S_ + i];
    red[tid] = s; __syncthreads();
    for (int off = 128; off > 0; off >>= 1) {
        if (tid < off) red[tid] += red[tid + off];
        __syncthreads();
    }
    int pos = red[0] - 1;
    const float* hr = hidden + ((size_t)(b * S_ + pos)) * H_;
    for (int i = tid; i < H_; i += 256) out[(size_t)b * H_ + i] = hr[i];
}

extern "C" void kernel_launch(void* const* d_in, const int* in_sizes, int n_in,
                              void* d_out, int out_size) {
    const int*   ids  = (const int*)d_in[0];
    const int*   mask = (const int*)d_in[1];
    const float* emb  = (const float*)d_in[2];
    const float* wq   = (const float*)d_in[3];
    const float* bq   = (const float*)d_in[4];
    const float* wk   = (const float*)d_in[5];
    const float* bk   = (const float*)d_in[6];
    const float* wv   = (const float*)d_in[7];
    const float* bv   = (const float*)d_in[8];
    const float* wo   = (const float*)d_in[9];
    const float* wg   = (const float*)d_in[10];
    const float* wu   = (const float*)d_in[11];
    const float* wd   = (const float*)d_in[12];
    const float* ln1  = (const float*)d_in[13];
    const float* ln2  = (const float*)d_in[14];
    const float* lnf  = (const float*)d_in[15];
    float* out = (float*)d_out;

    float *x, *h, *q, *k, *v, *att, *gate, *up;
    cudaGetSymbolAddress((void**)&x,    g_x);
    cudaGetSymbolAddress((void**)&h,    g_h);
    cudaGetSymbolAddress((void**)&q,    g_q);
    cudaGetSymbolAddress((void**)&k,    g_k);
    cudaGetSymbolAddress((void**)&v,    g_v);
    cudaGetSymbolAddress((void**)&att,  g_att);
    cudaGetSymbolAddress((void**)&gate, g_gate);
    cudaGetSymbolAddress((void**)&up,   g_up);

    static bool attr_set = false;
    if (!attr_set) {
        cudaFuncSetAttribute(qkv_kernel,
                             cudaFuncAttributeMaxDynamicSharedMemorySize, SMEM_BYTES);
        cudaFuncSetAttribute(gateup_kernel,
                             cudaFuncAttributeMaxDynamicSharedMemorySize, SMEM_BYTES);
        cudaFuncSetAttribute(mma_gemm_res,
                             cudaFuncAttributeMaxDynamicSharedMemorySize, SMEM_BYTES);
        attr_set = true;
    }

    embed_kernel<<<ROWS, 256>>>(ids, emb, x);

    for (int l = 0; l < L_; l++) {
        rmsnorm_kernel<<<ROWS, 256>>>(x, ln1 + (size_t)l * H_, h);

        qkv_kernel<<<dim3(16, ROWS / 128), 512, SMEM_BYTES>>>(
            h,
            wq + (size_t)l * H_ * QD,  bq + (size_t)l * QD,
            wk + (size_t)l * H_ * KVD, bk + (size_t)l * KVD,
            wv + (size_t)l * H_ * KVD, bv + (size_t)l * KVD,
            q, k, v);

        rope_kernel<<<ROWS, NH * 64>>>(q, NH);
        rope_kernel<<<ROWS, NKV * 64>>>(k, NKV);

        attn_kernel<<<B_ * NH * S_, 128>>>(q, k, v, mask, att);

        mma_gemm_res<<<dim3(H_ / 128, ROWS / 128), 512, SMEM_BYTES>>>(
            QD, H_, att, wo + (size_t)l * QD * H_, x, x);

        rmsnorm_kernel<<<ROWS, 256>>>(x, ln2 + (size_t)l * H_, h);

        gateup_kernel<<<dim3(140, ROWS / 128), 512, SMEM_BYTES>>>(
            h, wg + (size_t)l * H_ * F_, wu + (size_t)l * H_ * F_, gate, up);

        silu_mul_kernel<<<((size_t)ROWS * F_ + 255) / 256, 256>>>(gate, up, ROWS * F_);

        mma_gemm_res<<<dim3(H_ / 128, ROWS / 128), 512, SMEM_BYTES>>>(
            F_, H_, gate, wd + (size_t)l * F_ * H_, x, x);
    }

    rmsnorm_kernel<<<ROWS, 256>>>(x, lnf, out);
    last_kernel<<<B_, 256>>>(mask, out, out + (size_t)ROWS * H_);
}

// round 7
// speedup vs baseline: 1.4628x; 1.1787x over previous
#include <cuda_runtime.h>
#include <cuda_bf16.h>
#include <math.h>
#include <stdint.h>

// Problem constants (fixed by setup_inputs)
#define B_    2
#define S_    1024
#define ROWS  (B_*S_)       // 2048
#define H_    1536
#define F_    8960
#define L_    2
#define NH    12
#define NKV   2
#define DH    128
#define QD    (NH*DH)       // 1536
#define KVD   (NKV*DH)      // 256
#define EPS_  1e-6f

// Scratch (device globals: no allocation allowed)
__device__ float g_x  [ROWS*H_];
__device__ float g_h  [ROWS*H_];
__device__ float g_q  [ROWS*QD];
__device__ float g_k  [ROWS*KVD];
__device__ float g_v  [ROWS*KVD];
__device__ float g_att[ROWS*QD];
__device__ float g_gate[(size_t)ROWS*F_];
__device__ float g_up  [(size_t)ROWS*F_];

// ---------------- embedding gather ----------------
__global__ void embed_kernel(const int* __restrict__ ids,
                             const float* __restrict__ emb,
                             float* __restrict__ x) {
    int row = blockIdx.x;
    int id  = ids[row];
    const float* e = emb + (size_t)id * H_;
    float* xr = x + (size_t)row * H_;
    for (int i = threadIdx.x; i < H_; i += blockDim.x) xr[i] = e[i];
}

// ---------------- rmsnorm ----------------
__global__ void rmsnorm_kernel(const float* __restrict__ x,
                               const float* __restrict__ w,
                               float* __restrict__ out) {
    int row = blockIdx.x;
    const float* xr = x + (size_t)row * H_;
    int tid = threadIdx.x;            // 256
    float s = 0.f;
    for (int i = tid; i < H_; i += 256) { float v = xr[i]; s += v * v; }
    __shared__ float red[256];
    red[tid] = s; __syncthreads();
    for (int off = 128; off > 0; off >>= 1) {
        if (tid < off) red[tid] += red[tid + off];
        __syncthreads();
    }
    float rs = rsqrtf(red[0] / (float)H_ + EPS_);
    float* o = out + (size_t)row * H_;
    for (int i = tid; i < H_; i += 256) o[i] = xr[i] * rs * w[i];
}

// ---------------- bf16 split helpers ----------------
// pack two fp32 into bf16x2 (x -> low half, y -> high half), and the bf16x2 of residuals
__device__ __forceinline__ void split2(float x, float y, uint32_t& hi, uint32_t& lo) {
    asm("cvt.rn.bf16x2.f32 %0, %1, %2;" : "=r"(hi) : "f"(y), "f"(x));
    float hx = __uint_as_float(hi << 16);
    float hy = __uint_as_float(hi & 0xFFFF0000u);
    float rx = x - hx;
    float ry = y - hy;
    asm("cvt.rn.bf16x2.f32 %0, %1, %2;" : "=r"(lo) : "f"(ry), "f"(rx));
}

__device__ __forceinline__ void mma_bf16(float c[4], const uint32_t a[4], const uint32_t b[2]) {
    asm volatile(
        "mma.sync.aligned.m16n8k16.row.col.f32.bf16.bf16.f32 "
        "{%0,%1,%2,%3}, {%4,%5,%6,%7}, {%8,%9}, {%0,%1,%2,%3};"
        : "+f"(c[0]), "+f"(c[1]), "+f"(c[2]), "+f"(c[3])
        : "r"(a[0]), "r"(a[1]), "r"(a[2]), "r"(a[3]), "r"(b[0]), "r"(b[1]));
}

__device__ __forceinline__ void cp16(float* s, const float* g) {
    uint32_t sa = (uint32_t)__cvta_generic_to_shared(s);
    asm volatile("cp.async.cg.shared.global [%0], [%1], 16;" :: "r"(sa), "l"(g));
}

// ---------------- bf16x3 GEMM body: 512 threads, BM=BN=128, BK=32 ----------------
// 16 warps in 4x4 grid, each computes a 32x32 warp tile.
// k16 bf16 MMAs: hi*hi + lo*hi + hi*lo (lo*lo dropped, ~2^-18 rel).
// 2-stage cp.async double buffering of fp32 tiles. Requires K%32==0.
#define ASTRIDE 36
#define BSTRIDE 136
#define A_TILE (128 * ASTRIDE)
#define B_TILE (32 * BSTRIDE)
#define SMEM_BYTES ((2 * A_TILE + 2 * B_TILE) * 4)

template<bool BIAS, bool RES>
__device__ __forceinline__ void
gemm_body(int K, int lda, int ldb, int ldc,
          const float* __restrict__ Ag0,   // A + rowblock*lda
          const float* __restrict__ Bg0,   // B + colblock       (row stride ldb)
          const float* __restrict__ bias,  // bias + colblock
          const float* __restrict__ res,   // res + rowblock*ldc + colblock
          float* __restrict__ C,           // C   + rowblock*ldc + colblock
          float* smem) {
    float* Asb[2] = { smem, smem + A_TILE };
    float* Bsb[2] = { smem + 2 * A_TILE, smem + 2 * A_TILE + B_TILE };

    const int tid  = threadIdx.x;
    const int lane = tid & 31;
    const int wid  = tid >> 5;
    const int wm   = wid & 3;    // 0..3 : 32-row slab
    const int wn   = wid >> 2;   // 0..3 : 32-col slab

    const int a_row = tid >> 3;          // 0..63 (+64)
    const int a_col = (tid & 7) * 4;
    const int b_row = tid >> 5;          // 0..15 (+16)
    const int b_col = (tid & 31) * 4;
    const float* Ag = Ag0 + (size_t)a_row * lda + a_col;
    const float* Bg = Bg0 + (size_t)b_row * ldb + b_col;

    float acc[2][4][4];
    #pragma unroll
    for (int m = 0; m < 2; m++)
        #pragma unroll
        for (int n = 0; n < 4; n++)
            #pragma unroll
            for (int r = 0; r < 4; r++) acc[m][n][r] = 0.f;

    const int NT = K / 32;

    // prologue
    #pragma unroll
    for (int i = 0; i < 2; i++)
        cp16(Asb[0] + (a_row + i * 64) * ASTRIDE + a_col, Ag + (size_t)(i * 64) * lda);
    #pragma unroll
    for (int i = 0; i < 2; i++)
        cp16(Bsb[0] + (b_row + i * 16) * BSTRIDE + b_col, Bg + (size_t)(i * 16) * ldb);
    asm volatile("cp.async.commit_group;");

    const int fr  = lane >> 2;        // 0..7
    const int fk  = (lane & 3) * 2;   // 0,2,4,6 (k pair base)

    for (int t = 0; t < NT; t++) {
        if (t + 1 < NT) {
            const float* Agt = Ag + (t + 1) * 32;
            const float* Bgt = Bg + (size_t)(t + 1) * 32 * ldb;
            float* As1 = Asb[(t + 1) & 1];
            float* Bs1 = Bsb[(t + 1) & 1];
            #pragma unroll
            for (int i = 0; i < 2; i++)
                cp16(As1 + (a_row + i * 64) * ASTRIDE + a_col, Agt + (size_t)(i * 64) * lda);
            #pragma unroll
            for (int i = 0; i < 2; i++)
                cp16(Bs1 + (b_row + i * 16) * BSTRIDE + b_col, Bgt + (size_t)(i * 16) * ldb);
            asm volatile("cp.async.commit_group;");
            asm volatile("cp.async.wait_group 1;");
        } else {
            asm volatile("cp.async.wait_group 0;");
        }
        __syncthreads();

        const float* As = Asb[t & 1];
        const float* Bs = Bsb[t & 1];

        #pragma unroll
        for (int ks = 0; ks < 2; ks++) {
            const int k0 = ks * 16;
            uint32_t ah[2][4], al[2][4], bh[4][2], bl[4][2];
            #pragma unroll
            for (int m = 0; m < 2; m++) {
                const float* ap = As + (wm * 32 + m * 16 + fr) * ASTRIDE + k0 + fk;
                float2 p;
                p = *(const float2*)(ap);                   split2(p.x, p.y, ah[m][0], al[m][0]);
                p = *(const float2*)(ap + 8 * ASTRIDE);     split2(p.x, p.y, ah[m][1], al[m][1]);
                p = *(const float2*)(ap + 8);               split2(p.x, p.y, ah[m][2], al[m][2]);
                p = *(const float2*)(ap + 8 * ASTRIDE + 8); split2(p.x, p.y, ah[m][3], al[m][3]);
            }
            #pragma unroll
            for (int n = 0; n < 4; n++) {
                const float* bp = Bs + (k0 + fk) * BSTRIDE + wn * 32 + n * 8 + fr;
                split2(bp[0],           bp[BSTRIDE],     bh[n][0], bl[n][0]);
                split2(bp[8 * BSTRIDE], bp[9 * BSTRIDE], bh[n][1], bl[n][1]);
            }
            #pragma unroll
            for (int m = 0; m < 2; m++)
                #pragma unroll
                for (int n = 0; n < 4; n++) {
                    mma_bf16(acc[m][n], ah[m], bh[n]);
                    mma_bf16(acc[m][n], al[m], bh[n]);
                    mma_bf16(acc[m][n], ah[m], bl[n]);
                }
        }
        __syncthreads();
    }

    // epilogue (C fragment layout: rows fr/fr+8, cols (lane&3)*2 +{0,1})
    const int fc2 = (lane & 3) * 2;
    #pragma unroll
    for (int m = 0; m < 2; m++) {
        int row0 = wm * 32 + m * 16 + fr;
        #pragma unroll
        for (int n = 0; n < 4; n++) {
            int col = wn * 32 + n * 8 + fc2;
            float v0 = acc[m][n][0], v1 = acc[m][n][1];
            float v2 = acc[m][n][2], v3 = acc[m][n][3];
            if (BIAS) {
                float b0 = bias[col], b1 = bias[col + 1];
                v0 += b0; v1 += b1; v2 += b0; v3 += b1;
            }
            if (RES) {
                v0 += res[(size_t)row0 * ldc + col];
                v1 += res[(size_t)row0 * ldc + col + 1];
                v2 += res[(size_t)(row0 + 8) * ldc + col];
                v3 += res[(size_t)(row0 + 8) * ldc + col + 1];
            }
            C[(size_t)row0 * ldc + col]           = v0;
            C[(size_t)row0 * ldc + col + 1]       = v1;
            C[(size_t)(row0 + 8) * ldc + col]     = v2;
            C[(size_t)(row0 + 8) * ldc + col + 1] = v3;
        }
    }
}

// generic GEMM with residual (o-proj, down-proj)
__global__ void __launch_bounds__(512, 1)
mma_gemm_res(int K, int N,
             const float* __restrict__ A, const float* __restrict__ Bm,
             const float* __restrict__ res, float* __restrict__ C) {
    extern __shared__ float smem[];
    const int bx = blockIdx.x, by = blockIdx.y;
    gemm_body<false, true>(K, K, N, N,
                           A + (size_t)by * 128 * K,
                           Bm + bx * 128,
                           nullptr,
                           res + (size_t)by * 128 * N + bx * 128,
                           C + (size_t)by * 128 * N + bx * 128,
                           smem);
}

// fused QKV projection: grid.x = 16 (12 q blocks, 2 k, 2 v)
__global__ void __launch_bounds__(512, 1)
qkv_kernel(const float* __restrict__ A,
           const float* __restrict__ wq, const float* __restrict__ bq,
           const float* __restrict__ wk, const float* __restrict__ bk,
           const float* __restrict__ wv, const float* __restrict__ bv,
           float* __restrict__ q, float* __restrict__ k, float* __restrict__ v) {
    extern __shared__ float smem[];
    const int bx = blockIdx.x, by = blockIdx.y;
    const float *Bp, *bp; float* Cp; int ld, cb;
    if (bx < 12)      { cb = bx * 128;        Bp = wq; bp = bq; Cp = q; ld = QD;  }
    else if (bx < 14) { cb = (bx - 12) * 128; Bp = wk; bp = bk; Cp = k; ld = KVD; }
    else              { cb = (bx - 14) * 128; Bp = wv; bp = bv; Cp = v; ld = KVD; }
    gemm_body<true, false>(H_, H_, ld, ld,
                           A + (size_t)by * 128 * H_,
                           Bp + cb, bp + cb, nullptr,
                           Cp + (size_t)by * 128 * ld + cb,
                           smem);
}

// fused gate+up projection: grid.x = 140 (70 gate blocks, 70 up)
__global__ void __launch_bounds__(512, 1)
gateup_kernel(const float* __restrict__ A,
              const float* __restrict__ wg, const float* __restrict__ wu,
              float* __restrict__ gate, float* __restrict__ up) {
    extern __shared__ float smem[];
    const int bx = blockIdx.x, by = blockIdx.y;
    const float* Bp; float* Cp; int cb;
    if (bx < 70) { cb = bx * 128;        Bp = wg; Cp = gate; }
    else         { cb = (bx - 70) * 128; Bp = wu; Cp = up;   }
    gemm_body<false, false>(H_, H_, F_, F_,
                            A + (size_t)by * 128 * H_,
                            Bp + cb, nullptr, nullptr,
                            Cp + (size_t)by * 128 * F_ + cb,
                            smem);
}

// ---------------- RoPE (in place) ----------------
__global__ void rope_kernel(float* __restrict__ t, int nh) {
    int row = blockIdx.x;
    int tid = threadIdx.x;          // nh*64
    int hh = tid >> 6, d = tid & 63;
    int s = row % S_;
    float inv = expf(-(float)d * (13.815510557964274f / 64.0f));
    float ang = (float)s * inv;
    float sn, cs; sincosf(ang, &sn, &cs);
    float* p = t + (size_t)row * (nh * DH) + hh * DH + d;
    float x0 = p[0], x1 = p[64];
    p[0]  = x0 * cs - x1 * sn;
    p[64] = x1 * cs + x0 * sn;
}

// ---------------- attention: one block per (b, head, q-row), 128 threads ----------------
__global__ void attn_kernel(const float* __restrict__ q,
                            const float* __restrict__ k,
                            const float* __restrict__ v,
                            const int* __restrict__ mask,
                            float* __restrict__ out) {
    int blk = blockIdx.x;
    int b   = blk / (NH * S_);
    int rem = blk % (NH * S_);
    int h   = rem / S_;
    int qi  = rem % S_;
    int kvh = h / (NH / NKV);
    int tid = threadIdx.x;          // 128

    __shared__ float qs[DH];
    __shared__ float sc[128];
    __shared__ float red[128];

    const float* qrow = q + ((size_t)(b * S_ + qi)) * QD + h * DH;
    qs[tid] = qrow[tid];
    __syncthreads();

    float m = -1e30f, l = 0.f, acc = 0.f;
    const float scale = 0.08838834764831845f;

    for (int kc = 0; kc <= qi; kc += 128) {
        int len = min(128, qi + 1 - kc);
        int j = kc + tid;
        float s = -1e30f;
        bool valid = (tid < len) && (mask[b * S_ + j] > 0);
        if (valid) {
            const float4* kr = (const float4*)(k + ((size_t)(b * S_ + j)) * KVD + kvh * DH);
            const float4* qv = (const float4*)qs;
            float sum = 0.f;
            #pragma unroll
            for (int t = 0; t < 32; t++) {
                float4 a = qv[t]; float4 bb = kr[t];
                sum += a.x * bb.x + a.y * bb.y + a.z * bb.z + a.w * bb.w;
            }
            s = sum * scale;
        }
        red[tid] = s; __syncthreads();
        for (int off = 64; off > 0; off >>= 1) {
            if (tid < off) red[tid] = fmaxf(red[tid], red[tid + off]);
            __syncthreads();
        }
        float cmax = red[0];
        __syncthreads();
        float mnew = fmaxf(m, cmax);
        float p = valid ? expf(s - mnew) : 0.f;
        float alpha = expf(m - mnew);
        sc[tid] = p; red[tid] = p; __syncthreads();
        for (int off = 64; off > 0; off >>= 1) {
            if (tid < off) red[tid] += red[tid + off];
            __syncthreads();
        }
        float psum = red[0];
        l = l * alpha + psum;
        m = mnew;
        acc *= alpha;
        const float* vb = v + ((size_t)(b * S_ + kc)) * KVD + kvh * DH + tid;
        for (int jj = 0; jj < len; jj++) acc += sc[jj] * vb[(size_t)jj * KVD];
        __syncthreads();
    }
    out[((size_t)(b * S_ + qi)) * QD + h * DH + tid] = acc / l;
}

// ---------------- silu(gate) * up (in place into gate) ----------------
__global__ void silu_mul_kernel(float* __restrict__ g, const float* __restrict__ u, int n) {
    int i = blockIdx.x * blockDim.x + threadIdx.x;
    if (i < n) {
        float x = g[i];
        float s = x / (1.f + expf(-x));
        g[i] = s * u[i];
    }
}

// ---------------- last_hidden gather ----------------
__global__ void last_kernel(const int* __restrict__ mask,
                            const float* __restrict__ hidden,
                            float* __restrict__ out) {
    int b = blockIdx.x;
    int tid = threadIdx.x;  // 256
    __shared__ int red[256];
    int s = 0;
    for (int i = tid; i < S_; i += 256) s += mask[b * S_ + i];
    red[tid] = s; __syncthreads();
    for (int off = 128; off > 0; off >>= 1) {
        if (tid < off) red[tid] += red[tid + off];
        __syncthreads();
    }
    int pos = red[0] - 1;
    const float* hr = hidden + ((size_t)(b * S_ + pos)) * H_;
    for (int i = tid; i < H_; i += 256) out[(size_t)b * H_ + i] = hr[i];
}

extern "C" void kernel_launch(void* const* d_in, const int* in_sizes, int n_in,
                              void* d_out, int out_size) {
    const int*   ids  = (const int*)d_in[0];
    const int*   mask = (const int*)d_in[1];
    const float* emb  = (const float*)d_in[2];
    const float* wq   = (const float*)d_in[3];
    const float* bq   = (const float*)d_in[4];
    const float* wk   = (const float*)d_in[5];
    const float* bk   = (const float*)d_in[6];
    const float* wv   = (const float*)d_in[7];
    const float* bv   = (const float*)d_in[8];
    const float* wo   = (const float*)d_in[9];
    const float* wg   = (const float*)d_in[10];
    const float* wu   = (const float*)d_in[11];
    const float* wd   = (const float*)d_in[12];
    const float* ln1  = (const float*)d_in[13];
    const float* ln2  = (const float*)d_in[14];
    const float* lnf  = (const float*)d_in[15];
    float* out = (float*)d_out;

    float *x, *h, *q, *k, *v, *att, *gate, *up;
    cudaGetSymbolAddress((void**)&x,    g_x);
    cudaGetSymbolAddress((void**)&h,    g_h);
    cudaGetSymbolAddress((void**)&q,    g_q);
    cudaGetSymbolAddress((void**)&k,    g_k);
    cudaGetSymbolAddress((void**)&v,    g_v);
    cudaGetSymbolAddress((void**)&att,  g_att);
    cudaGetSymbolAddress((void**)&gate, g_gate);
    cudaGetSymbolAddress((void**)&up,   g_up);

    static bool attr_set = false;
    if (!attr_set) {
        cudaFuncSetAttribute(qkv_kernel,
                             cudaFuncAttributeMaxDynamicSharedMemorySize, SMEM_BYTES);
        cudaFuncSetAttribute(gateup_kernel,
                             cudaFuncAttributeMaxDynamicSharedMemorySize, SMEM_BYTES);
        cudaFuncSetAttribute(mma_gemm_res,
                             cudaFuncAttributeMaxDynamicSharedMemorySize, SMEM_BYTES);
        attr_set = true;
    }

    embed_kernel<<<ROWS, 256>>>(ids, emb, x);

    for (int l = 0; l < L_; l++) {
        rmsnorm_kernel<<<ROWS, 256>>>(x, ln1 + (size_t)l * H_, h);

        qkv_kernel<<<dim3(16, ROWS / 128), 512, SMEM_BYTES>>>(
            h,
            wq + (size_t)l * H_ * QD,  bq + (size_t)l * QD,
            wk + (size_t)l * H_ * KVD, bk + (size_t)l * KVD,
            wv + (size_t)l * H_ * KVD, bv + (size_t)l * KVD,
            q, k, v);

        rope_kernel<<<ROWS, NH * 64>>>(q, NH);
        rope_kernel<<<ROWS, NKV * 64>>>(k, NKV);

        attn_kernel<<<B_ * NH * S_, 128>>>(q, k, v, mask, att);

        mma_gemm_res<<<dim3(H_ / 128, ROWS / 128), 512, SMEM_BYTES>>>(
            QD, H_, att, wo + (size_t)l * QD * H_, x, x);

        rmsnorm_kernel<<<ROWS, 256>>>(x, ln2 + (size_t)l * H_, h);

        gateup_kernel<<<dim3(140, ROWS / 128), 512, SMEM_BYTES>>>(
            h, wg + (size_t)l * H_ * F_, wu + (size_t)l * H_ * F_, gate, up);

        silu_mul_kernel<<<((size_t)ROWS * F_ + 255) / 256, 256>>>(gate, up, ROWS * F_);

        mma_gemm_res<<<dim3(H_ / 128, ROWS / 128), 512, SMEM_BYTES>>>(
            F_, H_, gate, wd + (size_t)l * F_ * H_, x, x);
    }

    rmsnorm_kernel<<<ROWS, 256>>>(x, lnf, out);
    last_kernel<<<B_, 256>>>(mask, out, out + (size_t)ROWS * H_);
}

// round 8
// speedup vs baseline: 1.8364x; 1.2554x over previous
#include <cuda_runtime.h>
#include <cuda_bf16.h>
#include <math.h>
#include <stdint.h>

// Problem constants (fixed by setup_inputs)
#define B_    2
#define S_    1024
#define ROWS  (B_*S_)       // 2048
#define H_    1536
#define F_    8960
#define L_    2
#define NH    12
#define NKV   2
#define DH    128
#define QD    (NH*DH)       // 1536
#define KVD   (NKV*DH)      // 256
#define EPS_  1e-6f

// Weight-split segment sizes (elements) and per-layer offsets
#define WQ_SZ  (H_*QD)
#define WKV_SZ (H_*KVD)
#define WO_SZ  (QD*H_)
#define WGU_SZ (H_*F_)
#define WD_SZ  (F_*H_)
#define OFF_WQ 0
#define OFF_WK (OFF_WQ + WQ_SZ)
#define OFF_WV (OFF_WK + WKV_SZ)
#define OFF_WO (OFF_WV + WKV_SZ)
#define OFF_WG (OFF_WO + WO_SZ)
#define OFF_WU (OFF_WG + WGU_SZ)
#define OFF_WD (OFF_WU + WGU_SZ)
#define WLAYER (OFF_WD + WD_SZ)   // 46792704

// Scratch (device globals: no allocation allowed)
__device__ float g_x  [ROWS*H_];
__device__ __nv_bfloat16 g_hhi[ROWS*H_];
__device__ __nv_bfloat16 g_hlo[ROWS*H_];
__device__ float g_q  [ROWS*QD];
__device__ float g_k  [ROWS*KVD];
__device__ float g_v  [ROWS*KVD];
__device__ __nv_bfloat16 g_ahi[ROWS*QD];
__device__ __nv_bfloat16 g_alo[ROWS*QD];
__device__ float g_gate[(size_t)ROWS*F_];
__device__ float g_up  [(size_t)ROWS*F_];
__device__ __nv_bfloat16 g_ghi[(size_t)ROWS*F_];
__device__ __nv_bfloat16 g_glo[(size_t)ROWS*F_];
__device__ __nv_bfloat16 g_whi[(size_t)L_*WLAYER];
__device__ __nv_bfloat16 g_wlo[(size_t)L_*WLAYER];

typedef __nv_bfloat16 bf16;

__device__ __forceinline__ void split1(float x, bf16& h, bf16& l) {
    h = __float2bfloat16(x);
    l = __float2bfloat16(x - __bfloat162float(h));
}

// ---------------- weight split + transpose: W[K][N] fp32 -> hi/lo [N][K] bf16 ----------------
__global__ void wsplit_kernel(const float* __restrict__ W, int K, int N,
                              bf16* __restrict__ hi, bf16* __restrict__ lo) {
    __shared__ float t[32][33];
    const int n0 = blockIdx.x * 32, k0 = blockIdx.y * 32;
    const int tx = threadIdx.x, ty = threadIdx.y;   // 32 x 8
    #pragma unroll
    for (int j = 0; j < 4; j++)
        t[ty + 8 * j][tx] = W[(size_t)(k0 + ty + 8 * j) * N + n0 + tx];
    __syncthreads();
    #pragma unroll
    for (int j = 0; j < 4; j++) {
        int n = n0 + ty + 8 * j;
        float v = t[tx][ty + 8 * j];
        bf16 h, l; split1(v, h, l);
        hi[(size_t)n * K + k0 + tx] = h;
        lo[(size_t)n * K + k0 + tx] = l;
    }
}

// ---------------- embedding gather ----------------
__global__ void embed_kernel(const int* __restrict__ ids,
                             const float* __restrict__ emb,
                             float* __restrict__ x) {
    int row = blockIdx.x;
    int id  = ids[row];
    const float* e = emb + (size_t)id * H_;
    float* xr = x + (size_t)row * H_;
    for (int i = threadIdx.x; i < H_; i += blockDim.x) xr[i] = e[i];
}

// ---------------- rmsnorm -> hi/lo bf16 ----------------
__global__ void rmsnorm_split_kernel(const float* __restrict__ x,
                                     const float* __restrict__ w,
                                     bf16* __restrict__ ohi, bf16* __restrict__ olo) {
    int row = blockIdx.x;
    const float* xr = x + (size_t)row * H_;
    int tid = threadIdx.x;            // 256
    float s = 0.f;
    for (int i = tid; i < H_; i += 256) { float v = xr[i]; s += v * v; }
    __shared__ float red[256];
    red[tid] = s; __syncthreads();
    for (int off = 128; off > 0; off >>= 1) {
        if (tid < off) red[tid] += red[tid + off];
        __syncthreads();
    }
    float rs = rsqrtf(red[0] / (float)H_ + EPS_);
    for (int i = tid; i < H_; i += 256) {
        float v = xr[i] * rs * w[i];
        bf16 h, l; split1(v, h, l);
        ohi[(size_t)row * H_ + i] = h;
        olo[(size_t)row * H_ + i] = l;
    }
}

// ---------------- rmsnorm -> fp32 (final) ----------------
__global__ void rmsnorm_kernel(const float* __restrict__ x,
                               const float* __restrict__ w,
                               float* __restrict__ out) {
    int row = blockIdx.x;
    const float* xr = x + (size_t)row * H_;
    int tid = threadIdx.x;
    float s = 0.f;
    for (int i = tid; i < H_; i += 256) { float v = xr[i]; s += v * v; }
    __shared__ float red[256];
    red[tid] = s; __syncthreads();
    for (int off = 128; off > 0; off >>= 1) {
        if (tid < off) red[tid] += red[tid + off];
        __syncthreads();
    }
    float rs = rsqrtf(red[0] / (float)H_ + EPS_);
    float* o = out + (size_t)row * H_;
    for (int i = tid; i < H_; i += 256) o[i] = xr[i] * rs * w[i];
}

// ---------------- MMA + cp.async helpers ----------------
__device__ __forceinline__ void mma_bf16(float c[4], const uint32_t a[4], const uint32_t b[2]) {
    asm volatile(
        "mma.sync.aligned.m16n8k16.row.col.f32.bf16.bf16.f32 "
        "{%0,%1,%2,%3}, {%4,%5,%6,%7}, {%8,%9}, {%0,%1,%2,%3};"
        : "+f"(c[0]), "+f"(c[1]), "+f"(c[2]), "+f"(c[3])
        : "r"(a[0]), "r"(a[1]), "r"(a[2]), "r"(a[3]), "r"(b[0]), "r"(b[1]));
}

__device__ __forceinline__ void cp16(void* s, const void* g) {
    uint32_t sa = (uint32_t)__cvta_generic_to_shared(s);
    asm volatile("cp.async.cg.shared.global [%0], [%1], 16;" :: "r"(sa), "l"(g));
}

// ---------------- bf16x3 GEMM body (pre-split inputs): 512 threads, BM=BN=128, BK=32 ----------------
// A: hi/lo bf16 [row][K]; B: hi/lo bf16 [n][K] (pre-transposed weight).
// smem tile: 128 rows x 80B (64B = 32 bf16 data + 16B pad). 4 tiles x 2 stages = 80KB.
#define TSTRIDE 80
#define TILE_B (128 * TSTRIDE)            // 10240
#define STAGE_B (4 * TILE_B)              // 40960
#define SMEM_BYTES (2 * STAGE_B)          // 81920
#define T_AHI 0
#define T_ALO TILE_B
#define T_BHI (2 * TILE_B)
#define T_BLO (3 * TILE_B)

template<bool BIAS, bool RES>
__device__ __forceinline__ void
gemm_body(int K, int ldc,
          const bf16* __restrict__ Ahi, const bf16* __restrict__ Alo,   // + rowblock*K
          const bf16* __restrict__ Bhi, const bf16* __restrict__ Blo,   // + n0*K
          const float* __restrict__ bias,                               // + n0
          const float* __restrict__ res,                                // + rowblock*ldc + n0
          float* __restrict__ C,                                        // + rowblock*ldc + n0
          char* smem) {
    const int tid  = threadIdx.x;
    const int lane = tid & 31;
    const int wid  = tid >> 5;
    const int wm   = wid & 3;
    const int wn   = wid >> 2;

    const int row = tid >> 2;     // 0..127
    const int ch  = tid & 3;      // 16B chunk within 64B row
    const size_t gRow = (size_t)row * K + ch * 8;
    const uint32_t sOff = (uint32_t)(row * TSTRIDE + ch * 16);

    float acc[2][4][4];
    #pragma unroll
    for (int m = 0; m < 2; m++)
        #pragma unroll
        for (int n = 0; n < 4; n++)
            #pragma unroll
            for (int r = 0; r < 4; r++) acc[m][n][r] = 0.f;

    const int NT = K / 32;

    // prologue: stage 0
    cp16(smem + T_AHI + sOff, Ahi + gRow);
    cp16(smem + T_ALO + sOff, Alo + gRow);
    cp16(smem + T_BHI + sOff, Bhi + gRow);
    cp16(smem + T_BLO + sOff, Blo + gRow);
    asm volatile("cp.async.commit_group;");

    const int fr = lane >> 2;
    const int fp = (lane & 3) * 4;   // byte offset of k-pair within quarter

    for (int t = 0; t < NT; t++) {
        if (t + 1 < NT) {
            char* s1 = smem + ((t + 1) & 1) * STAGE_B;
            size_t g1 = gRow + (size_t)(t + 1) * 32;
            cp16(s1 + T_AHI + sOff, Ahi + g1);
            cp16(s1 + T_ALO + sOff, Alo + g1);
            cp16(s1 + T_BHI + sOff, Bhi + g1);
            cp16(s1 + T_BLO + sOff, Blo + g1);
            asm volatile("cp.async.commit_group;");
            asm volatile("cp.async.wait_group 1;");
        } else {
            asm volatile("cp.async.wait_group 0;");
        }
        __syncthreads();

        const char* sb = smem + (t & 1) * STAGE_B;

        #pragma unroll
        for (int ks = 0; ks < 2; ks++) {
            const int pb = fp + ks * 32;    // byte offset of k pair (8 pairs per ks half)
            uint32_t ah[2][4], al[2][4], bh[4][2], bl[4][2];
            #pragma unroll
            for (int m = 0; m < 2; m++) {
                const int off = (wm * 32 + m * 16 + fr) * TSTRIDE + pb;
                ah[m][0] = *(const uint32_t*)(sb + T_AHI + off);
                ah[m][1] = *(const uint32_t*)(sb + T_AHI + off + 8 * TSTRIDE);
                ah[m][2] = *(const uint32_t*)(sb + T_AHI + off + 16);
                ah[m][3] = *(const uint32_t*)(sb + T_AHI + off + 8 * TSTRIDE + 16);
                al[m][0] = *(const uint32_t*)(sb + T_ALO + off);
                al[m][1] = *(const uint32_t*)(sb + T_ALO + off + 8 * TSTRIDE);
                al[m][2] = *(const uint32_t*)(sb + T_ALO + off + 16);
                al[m][3] = *(const uint32_t*)(sb + T_ALO + off + 8 * TSTRIDE + 16);
            }
            #pragma unroll
            for (int n = 0; n < 4; n++) {
                const int off = (wn * 32 + n * 8 + fr) * TSTRIDE + pb;
                bh[n][0] = *(const uint32_t*)(sb + T_BHI + off);
                bh[n][1] = *(const uint32_t*)(sb + T_BHI + off + 16);
                bl[n][0] = *(const uint32_t*)(sb + T_BLO + off);
                bl[n][1] = *(const uint32_t*)(sb + T_BLO + off + 16);
            }
            #pragma unroll
            for (int m = 0; m < 2; m++)
                #pragma unroll
                for (int n = 0; n < 4; n++) {
                    mma_bf16(acc[m][n], ah[m], bh[n]);
                    mma_bf16(acc[m][n], al[m], bh[n]);
                    mma_bf16(acc[m][n], ah[m], bl[n]);
                }
        }
        __syncthreads();
    }

    // epilogue
    const int fc2 = (lane & 3) * 2;
    #pragma unroll
    for (int m = 0; m < 2; m++) {
        int row0 = wm * 32 + m * 16 + fr;
        #pragma unroll
        for (int n = 0; n < 4; n++) {
            int col = wn * 32 + n * 8 + fc2;
            float v0 = acc[m][n][0], v1 = acc[m][n][1];
            float v2 = acc[m][n][2], v3 = acc[m][n][3];
            if (BIAS) {
                float b0 = bias[col], b1 = bias[col + 1];
                v0 += b0; v1 += b1; v2 += b0; v3 += b1;
            }
            if (RES) {
                v0 += res[(size_t)row0 * ldc + col];
                v1 += res[(size_t)row0 * ldc + col + 1];
                v2 += res[(size_t)(row0 + 8) * ldc + col];
                v3 += res[(size_t)(row0 + 8) * ldc + col + 1];
            }
            C[(size_t)row0 * ldc + col]           = v0;
            C[(size_t)row0 * ldc + col + 1]       = v1;
            C[(size_t)(row0 + 8) * ldc + col]     = v2;
            C[(size_t)(row0 + 8) * ldc + col + 1] = v3;
        }
    }
}

// generic GEMM with residual (o-proj K=QD, down-proj K=F), N=H
__global__ void __launch_bounds__(512, 1)
mma_gemm_res(int K,
             const bf16* __restrict__ Ahi, const bf16* __restrict__ Alo,
             const bf16* __restrict__ Whi, const bf16* __restrict__ Wlo,
             const float* __restrict__ res, float* __restrict__ C) {
    extern __shared__ char smem[];
    const int bx = blockIdx.x, by = blockIdx.y;
    gemm_body<false, true>(K, H_,
                           Ahi + (size_t)by * 128 * K, Alo + (size_t)by * 128 * K,
                           Whi + (size_t)bx * 128 * K, Wlo + (size_t)bx * 128 * K,
                           nullptr,
                           res + (size_t)by * 128 * H_ + bx * 128,
                           C + (size_t)by * 128 * H_ + bx * 128,
                           smem);
}

// fused QKV projection: grid.x = 16 (12 q blocks, 2 k, 2 v); K = H
__global__ void __launch_bounds__(512, 1)
qkv_kernel(const bf16* __restrict__ Ahi, const bf16* __restrict__ Alo,
           const bf16* __restrict__ whi, const bf16* __restrict__ wlo,   // layer base
           const float* __restrict__ bq, const float* __restrict__ bk,
           const float* __restrict__ bv,
           float* __restrict__ q, float* __restrict__ k, float* __restrict__ v) {
    extern __shared__ char smem[];
    const int bx = blockIdx.x, by = blockIdx.y;
    size_t seg; const float* bp; float* Cp; int ld, n0;
    if (bx < 12)      { seg = OFF_WQ; n0 = bx * 128;        bp = bq; Cp = q; ld = QD;  }
    else if (bx < 14) { seg = OFF_WK; n0 = (bx - 12) * 128; bp = bk; Cp = k; ld = KVD; }
    else              { seg = OFF_WV; n0 = (bx - 14) * 128; bp = bv; Cp = v; ld = KVD; }
    gemm_body<true, false>(H_, ld,
                           Ahi + (size_t)by * 128 * H_, Alo + (size_t)by * 128 * H_,
                           whi + seg + (size_t)n0 * H_, wlo + seg + (size_t)n0 * H_,
                           bp + n0, nullptr,
                           Cp + (size_t)by * 128 * ld + n0,
                           smem);
}

// fused gate+up projection: grid.x = 140 (70 gate, 70 up); K = H, ldc = F
__global__ void __launch_bounds__(512, 1)
gateup_kernel(const bf16* __restrict__ Ahi, const bf16* __restrict__ Alo,
              const bf16* __restrict__ whi, const bf16* __restrict__ wlo,  // layer base
              float* __restrict__ gate, float* __restrict__ up) {
    extern __shared__ char smem[];
    const int bx = blockIdx.x, by = blockIdx.y;
    size_t seg; float* Cp; int n0;
    if (bx < 70) { seg = OFF_WG; n0 = bx * 128;        Cp = gate; }
    else         { seg = OFF_WU; n0 = (bx - 70) * 128; Cp = up;   }
    gemm_body<false, false>(H_, F_,
                            Ahi + (size_t)by * 128 * H_, Alo + (size_t)by * 128 * H_,
                            whi + seg + (size_t)n0 * H_, wlo + seg + (size_t)n0 * H_,
                            nullptr, nullptr,
                            Cp + (size_t)by * 128 * F_ + n0,
                            smem);
}

// ---------------- RoPE (in place) ----------------
__global__ void rope_kernel(float* __restrict__ t, int nh) {
    int row = blockIdx.x;
    int tid = threadIdx.x;          // nh*64
    int hh = tid >> 6, d = tid & 63;
    int s = row % S_;
    float inv = expf(-(float)d * (13.815510557964274f / 64.0f));
    float ang = (float)s * inv;
    float sn, cs; sincosf(ang, &sn, &cs);
    float* p = t + (size_t)row * (nh * DH) + hh * DH + d;
    float x0 = p[0], x1 = p[64];
    p[0]  = x0 * cs - x1 * sn;
    p[64] = x1 * cs + x0 * sn;
}

// ---------------- attention: one block per (b, head, q-row), 128 threads ----------------
__global__ void attn_kernel(const float* __restrict__ q,
                            const float* __restrict__ k,
                            const float* __restrict__ v,
                            const int* __restrict__ mask,
                            bf16* __restrict__ ohi, bf16* __restrict__ olo) {
    int blk = blockIdx.x;
    int b   = blk / (NH * S_);
    int rem = blk % (NH * S_);
    int h   = rem / S_;
    int qi  = rem % S_;
    int kvh = h / (NH / NKV);
    int tid = threadIdx.x;          // 128

    __shared__ float qs[DH];
    __shared__ float sc[128];
    __shared__ float red[128];

    const float* qrow = q + ((size_t)(b * S_ + qi)) * QD + h * DH;
    qs[tid] = qrow[tid];
    __syncthreads();

    float m = -1e30f, l = 0.f, acc = 0.f;
    const float scale = 0.08838834764831845f;

    for (int kc = 0; kc <= qi; kc += 128) {
        int len = min(128, qi + 1 - kc);
        int j = kc + tid;
        float s = -1e30f;
        bool valid = (tid < len) && (mask[b * S_ + j] > 0);
        if (valid) {
            const float4* kr = (const float4*)(k + ((size_t)(b * S_ + j)) * KVD + kvh * DH);
            const float4* qv = (const float4*)qs;
            float sum = 0.f;
            #pragma unroll
            for (int t = 0; t < 32; t++) {
                float4 a = qv[t]; float4 bb = kr[t];
                sum += a.x * bb.x + a.y * bb.y + a.z * bb.z + a.w * bb.w;
            }
            s = sum * scale;
        }
        red[tid] = s; __syncthreads();
        for (int off = 64; off > 0; off >>= 1) {
            if (tid < off) red[tid] = fmaxf(red[tid], red[tid + off]);
            __syncthreads();
        }
        float cmax = red[0];
        __syncthreads();
        float mnew = fmaxf(m, cmax);
        float p = valid ? expf(s - mnew) : 0.f;
        float alpha = expf(m - mnew);
        sc[tid] = p; red[tid] = p; __syncthreads();
        for (int off = 64; off > 0; off >>= 1) {
            if (tid < off) red[tid] += red[tid + off];
            __syncthreads();
        }
        float psum = red[0];
        l = l * alpha + psum;
        m = mnew;
        acc *= alpha;
        const float* vb = v + ((size_t)(b * S_ + kc)) * KVD + kvh * DH + tid;
        for (int jj = 0; jj < len; jj++) acc += sc[jj] * vb[(size_t)jj * KVD];
        __syncthreads();
    }
    float o = acc / l;
    bf16 hh2, ll2; split1(o, hh2, ll2);
    size_t idx = ((size_t)(b * S_ + qi)) * QD + h * DH + tid;
    ohi[idx] = hh2;
    olo[idx] = ll2;
}

// ---------------- silu(gate) * up -> hi/lo bf16 ----------------
__global__ void silu_mul_kernel(const float* __restrict__ g, const float* __restrict__ u,
                                bf16* __restrict__ ohi, bf16* __restrict__ olo, size_t n) {
    size_t i = (size_t)blockIdx.x * blockDim.x + threadIdx.x;
    if (i < n) {
        float x = g[i];
        float s = x / (1.f + expf(-x));
        float v = s * u[i];
        bf16 h, l; split1(v, h, l);
        ohi[i] = h; olo[i] = l;
    }
}

// ---------------- last_hidden gather ----------------
__global__ void last_kernel(const int* __restrict__ mask,
                            const float* __restrict__ hidden,
                            float* __restrict__ out) {
    int b = blockIdx.x;
    int tid = threadIdx.x;  // 256
    __shared__ int red[256];
    int s = 0;
    for (int i = tid; i < S_; i += 256) s += mask[b * S_ + i];
    red[tid] = s; __syncthreads();
    for (int off = 128; off > 0; off >>= 1) {
        if (tid < off) red[tid] += red[tid + off];
        __syncthreads();
    }
    int pos = red[0] - 1;
    const float* hr = hidden + ((size_t)(b * S_ + pos)) * H_;
    for (int i = tid; i < H_; i += 256) out[(size_t)b * H_ + i] = hr[i];
}

extern "C" void kernel_launch(void* const* d_in, const int* in_sizes, int n_in,
                              void* d_out, int out_size) {
    const int*   ids  = (const int*)d_in[0];
    const int*   mask = (const int*)d_in[1];
    const float* emb  = (const float*)d_in[2];
    const float* wq   = (const float*)d_in[3];
    const float* bq   = (const float*)d_in[4];
    const float* wk   = (const float*)d_in[5];
    const float* bk   = (const float*)d_in[6];
    const float* wv   = (const float*)d_in[7];
    const float* bv   = (const float*)d_in[8];
    const float* wo   = (const float*)d_in[9];
    const float* wg   = (const float*)d_in[10];
    const float* wu   = (const float*)d_in[11];
    const float* wd   = (const float*)d_in[12];
    const float* ln1  = (const float*)d_in[13];
    const float* ln2  = (const float*)d_in[14];
    const float* lnf  = (const float*)d_in[15];
    float* out = (float*)d_out;

    float *x, *q, *k, *v, *gate, *up;
    bf16 *hhi, *hlo, *ahi, *alo, *ghi, *glo, *whi, *wlo;
    cudaGetSymbolAddress((void**)&x,    g_x);
    cudaGetSymbolAddress((void**)&hhi,  g_hhi);
    cudaGetSymbolAddress((void**)&hlo,  g_hlo);
    cudaGetSymbolAddress((void**)&q,    g_q);
    cudaGetSymbolAddress((void**)&k,    g_k);
    cudaGetSymbolAddress((void**)&v,    g_v);
    cudaGetSymbolAddress((void**)&ahi,  g_ahi);
    cudaGetSymbolAddress((void**)&alo,  g_alo);
    cudaGetSymbolAddress((void**)&gate, g_gate);
    cudaGetSymbolAddress((void**)&up,   g_up);
    cudaGetSymbolAddress((void**)&ghi,  g_ghi);
    cudaGetSymbolAddress((void**)&glo,  g_glo);
    cudaGetSymbolAddress((void**)&whi,  g_whi);
    cudaGetSymbolAddress((void**)&wlo,  g_wlo);

    static bool attr_set = false;
    if (!attr_set) {
        cudaFuncSetAttribute(qkv_kernel,
                             cudaFuncAttributeMaxDynamicSharedMemorySize, SMEM_BYTES);
        cudaFuncSetAttribute(gateup_kernel,
                             cudaFuncAttributeMaxDynamicSharedMemorySize, SMEM_BYTES);
        cudaFuncSetAttribute(mma_gemm_res,
                             cudaFuncAttributeMaxDynamicSharedMemorySize, SMEM_BYTES);
        attr_set = true;
    }

    // pre-split + transpose all weights (constant inputs)
    dim3 wb(32, 8);
    for (int l = 0; l < L_; l++) {
        bf16* Whi = whi + (size_t)l * WLAYER;
        bf16* Wlo = wlo + (size_t)l * WLAYER;
        wsplit_kernel<<<dim3(QD / 32, H_ / 32), wb>>>(wq + (size_t)l * H_ * QD,  H_, QD,  Whi + OFF_WQ, Wlo + OFF_WQ);
        wsplit_kernel<<<dim3(KVD / 32, H_ / 32), wb>>>(wk + (size_t)l * H_ * KVD, H_, KVD, Whi + OFF_WK, Wlo + OFF_WK);
        wsplit_kernel<<<dim3(KVD / 32, H_ / 32), wb>>>(wv + (size_t)l * H_ * KVD, H_, KVD, Whi + OFF_WV, Wlo + OFF_WV);
        wsplit_kernel<<<dim3(H_ / 32, QD / 32), wb>>>(wo + (size_t)l * QD * H_,  QD, H_,  Whi + OFF_WO, Wlo + OFF_WO);
        wsplit_kernel<<<dim3(F_ / 32, H_ / 32), wb>>>(wg + (size_t)l * H_ * F_,  H_, F_,  Whi + OFF_WG, Wlo + OFF_WG);
        wsplit_kernel<<<dim3(F_ / 32, H_ / 32), wb>>>(wu + (size_t)l * H_ * F_,  H_, F_,  Whi + OFF_WU, Wlo + OFF_WU);
        wsplit_kernel<<<dim3(H_ / 32, F_ / 32), wb>>>(wd + (size_t)l * F_ * H_,  F_, H_,  Whi + OFF_WD, Wlo + OFF_WD);
    }

    embed_kernel<<<ROWS, 256>>>(ids, emb, x);

    for (int l = 0; l < L_; l++) {
        const bf16* Whi = whi + (size_t)l * WLAYER;
        const bf16* Wlo = wlo + (size_t)l * WLAYER;

        rmsnorm_split_kernel<<<ROWS, 256>>>(x, ln1 + (size_t)l * H_, hhi, hlo);

        qkv_kernel<<<dim3(16, ROWS / 128), 512, SMEM_BYTES>>>(
            hhi, hlo, Whi, Wlo,
            bq + (size_t)l * QD, bk + (size_t)l * KVD, bv + (size_t)l * KVD,
            q, k, v);

        rope_kernel<<<ROWS, NH * 64>>>(q, NH);
        rope_kernel<<<ROWS, NKV * 64>>>(k, NKV);

        attn_kernel<<<B_ * NH * S_, 128>>>(q, k, v, mask, ahi, alo);

        mma_gemm_res<<<dim3(H_ / 128, ROWS / 128), 512, SMEM_BYTES>>>(
            QD, ahi, alo, Whi + OFF_WO, Wlo + OFF_WO, x, x);

        rmsnorm_split_kernel<<<ROWS, 256>>>(x, ln2 + (size_t)l * H_, hhi, hlo);

        gateup_kernel<<<dim3(140, ROWS / 128), 512, SMEM_BYTES>>>(
            hhi, hlo, Whi, Wlo, gate, up);

        silu_mul_kernel<<<((size_t)ROWS * F_ + 255) / 256, 256>>>(
            gate, up, ghi, glo, (size_t)ROWS * F_);

        mma_gemm_res<<<dim3(H_ / 128, ROWS / 128), 512, SMEM_BYTES>>>(
            F_, ghi, glo, Whi + OFF_WD, Wlo + OFF_WD, x, x);
    }

    rmsnorm_kernel<<<ROWS, 256>>>(x, lnf, out);
    last_kernel<<<B_, 256>>>(mask, out, out + (size_t)ROWS * H_);
}

// round 9
// speedup vs baseline: 1.8834x; 1.0256x over previous
#include <cuda_runtime.h>
#include <cuda_bf16.h>
#include <math.h>
#include <stdint.h>

// Problem constants (fixed by setup_inputs)
#define B_    2
#define S_    1024
#define ROWS  (B_*S_)       // 2048
#define H_    1536
#define F_    8960
#define L_    2
#define NH    12
#define NKV   2
#define DH    128
#define QD    (NH*DH)       // 1536
#define KVD   (NKV*DH)      // 256
#define EPS_  1e-6f

// Weight-split segment sizes (elements) and per-layer offsets
#define WQ_SZ  (H_*QD)
#define WKV_SZ (H_*KVD)
#define WO_SZ  (QD*H_)
#define WGU_SZ (H_*F_)
#define WD_SZ  (F_*H_)
#define OFF_WQ 0
#define OFF_WK (OFF_WQ + WQ_SZ)
#define OFF_WV (OFF_WK + WKV_SZ)
#define OFF_WO (OFF_WV + WKV_SZ)
#define OFF_WG (OFF_WO + WO_SZ)
#define OFF_WU (OFF_WG + WGU_SZ)
#define OFF_WD (OFF_WU + WGU_SZ)
#define WLAYER (OFF_WD + WD_SZ)

// Scratch (device globals: no allocation allowed)
__device__ float g_x  [ROWS*H_];
__device__ __nv_bfloat16 g_hhi[ROWS*H_];
__device__ __nv_bfloat16 g_hlo[ROWS*H_];
__device__ float g_q  [ROWS*QD];
__device__ float g_k  [ROWS*KVD];
__device__ float g_v  [ROWS*KVD];
__device__ __nv_bfloat16 g_ahi[ROWS*QD];
__device__ __nv_bfloat16 g_alo[ROWS*QD];
__device__ float g_gate[(size_t)ROWS*F_];
__device__ float g_up  [(size_t)ROWS*F_];
__device__ __nv_bfloat16 g_ghi[(size_t)ROWS*F_];
__device__ __nv_bfloat16 g_glo[(size_t)ROWS*F_];
__device__ __nv_bfloat16 g_whi[(size_t)L_*WLAYER];
__device__ __nv_bfloat16 g_wlo[(size_t)L_*WLAYER];

typedef __nv_bfloat16 bf16;

__device__ __forceinline__ void split1(float x, bf16& h, bf16& l) {
    h = __float2bfloat16(x);
    l = __float2bfloat16(x - __bfloat162float(h));
}

// ---------------- weight split + transpose: W[K][N] fp32 -> hi/lo [N][K] bf16 ----------------
__global__ void wsplit_kernel(const float* __restrict__ W, int K, int N,
                              bf16* __restrict__ hi, bf16* __restrict__ lo) {
    __shared__ float t[32][33];
    const int n0 = blockIdx.x * 32, k0 = blockIdx.y * 32;
    const int tx = threadIdx.x, ty = threadIdx.y;   // 32 x 8
    #pragma unroll
    for (int j = 0; j < 4; j++)
        t[ty + 8 * j][tx] = W[(size_t)(k0 + ty + 8 * j) * N + n0 + tx];
    __syncthreads();
    #pragma unroll
    for (int j = 0; j < 4; j++) {
        int n = n0 + ty + 8 * j;
        float v = t[tx][ty + 8 * j];
        bf16 h, l; split1(v, h, l);
        hi[(size_t)n * K + k0 + tx] = h;
        lo[(size_t)n * K + k0 + tx] = l;
    }
}

// ---------------- embedding gather ----------------
__global__ void embed_kernel(const int* __restrict__ ids,
                             const float* __restrict__ emb,
                             float* __restrict__ x) {
    int row = blockIdx.x;
    int id  = ids[row];
    const float* e = emb + (size_t)id * H_;
    float* xr = x + (size_t)row * H_;
    for (int i = threadIdx.x; i < H_; i += blockDim.x) xr[i] = e[i];
}

// ---------------- rmsnorm -> hi/lo bf16 ----------------
__global__ void rmsnorm_split_kernel(const float* __restrict__ x,
                                     const float* __restrict__ w,
                                     bf16* __restrict__ ohi, bf16* __restrict__ olo) {
    int row = blockIdx.x;
    const float* xr = x + (size_t)row * H_;
    int tid = threadIdx.x;            // 256
    float s = 0.f;
    for (int i = tid; i < H_; i += 256) { float v = xr[i]; s += v * v; }
    __shared__ float red[256];
    red[tid] = s; __syncthreads();
    for (int off = 128; off > 0; off >>= 1) {
        if (tid < off) red[tid] += red[tid + off];
        __syncthreads();
    }
    float rs = rsqrtf(red[0] / (float)H_ + EPS_);
    for (int i = tid; i < H_; i += 256) {
        float v = xr[i] * rs * w[i];
        bf16 h, l; split1(v, h, l);
        ohi[(size_t)row * H_ + i] = h;
        olo[(size_t)row * H_ + i] = l;
    }
}

// ---------------- rmsnorm -> fp32 (final) ----------------
__global__ void rmsnorm_kernel(const float* __restrict__ x,
                               const float* __restrict__ w,
                               float* __restrict__ out) {
    int row = blockIdx.x;
    const float* xr = x + (size_t)row * H_;
    int tid = threadIdx.x;
    float s = 0.f;
    for (int i = tid; i < H_; i += 256) { float v = xr[i]; s += v * v; }
    __shared__ float red[256];
    red[tid] = s; __syncthreads();
    for (int off = 128; off > 0; off >>= 1) {
        if (tid < off) red[tid] += red[tid + off];
        __syncthreads();
    }
    float rs = rsqrtf(red[0] / (float)H_ + EPS_);
    float* o = out + (size_t)row * H_;
    for (int i = tid; i < H_; i += 256) o[i] = xr[i] * rs * w[i];
}

// ---------------- MMA + cp.async + ldmatrix helpers ----------------
__device__ __forceinline__ void mma_bf16(float c[4], const uint32_t a[4], const uint32_t b[2]) {
    asm volatile(
        "mma.sync.aligned.m16n8k16.row.col.f32.bf16.bf16.f32 "
        "{%0,%1,%2,%3}, {%4,%5,%6,%7}, {%8,%9}, {%0,%1,%2,%3};"
        : "+f"(c[0]), "+f"(c[1]), "+f"(c[2]), "+f"(c[3])
        : "r"(a[0]), "r"(a[1]), "r"(a[2]), "r"(a[3]), "r"(b[0]), "r"(b[1]));
}

__device__ __forceinline__ void cp16(void* s, const void* g) {
    uint32_t sa = (uint32_t)__cvta_generic_to_shared(s);
    asm volatile("cp.async.cg.shared.global [%0], [%1], 16;" :: "r"(sa), "l"(g));
}

__device__ __forceinline__ void ldm_x4(uint32_t& r0, uint32_t& r1, uint32_t& r2, uint32_t& r3,
                                       uint32_t addr) {
    asm volatile("ldmatrix.sync.aligned.m8n8.x4.shared.b16 {%0,%1,%2,%3}, [%4];"
                 : "=r"(r0), "=r"(r1), "=r"(r2), "=r"(r3) : "r"(addr));
}

// ---------------- bf16x3 GEMM body (pre-split inputs, ldmatrix): 512 threads, BM=BN=128, BK=32 ----------------
#define TSTRIDE 80
#define TILE_B (128 * TSTRIDE)            // 10240
#define STAGE_B (4 * TILE_B)              // 40960
#define SMEM_BYTES (2 * STAGE_B)          // 81920
#define T_AHI 0
#define T_ALO TILE_B
#define T_BHI (2 * TILE_B)
#define T_BLO (3 * TILE_B)

template<bool BIAS, bool RES>
__device__ __forceinline__ void
gemm_body(int K, int ldc,
          const bf16* __restrict__ Ahi, const bf16* __restrict__ Alo,   // + rowblock*K
          const bf16* __restrict__ Bhi, const bf16* __restrict__ Blo,   // + n0*K
          const float* __restrict__ bias,                               // + n0
          const float* __restrict__ res,                                // + rowblock*ldc + n0
          float* __restrict__ C,                                        // + rowblock*ldc + n0
          char* smem) {
    const int tid  = threadIdx.x;
    const int lane = tid & 31;
    const int wid  = tid >> 5;
    const int wm   = wid & 3;
    const int wn   = wid >> 2;

    const int row = tid >> 2;     // 0..127
    const int ch  = tid & 3;      // 16B chunk within 64B row
    const size_t gRow = (size_t)row * K + ch * 8;
    const uint32_t sOff = (uint32_t)(row * TSTRIDE + ch * 16);

    const uint32_t smemBase = (uint32_t)__cvta_generic_to_shared(smem);

    // ldmatrix lane mappings
    const int lj = lane >> 3;     // matrix index 0..3
    const int lr = lane & 7;      // row within matrix
    // A: matrix j -> row +((j&1)*8), byte +((j>>1)*16)
    uint32_t aoff[2];
    #pragma unroll
    for (int m = 0; m < 2; m++)
        aoff[m] = (uint32_t)((wm * 32 + m * 16 + (lj & 1) * 8 + lr) * TSTRIDE + (lj >> 1) * 16);
    // B: matrix j -> n row +((j>>1)*8), byte +((j&1)*16)
    uint32_t boff[2];
    #pragma unroll
    for (int p = 0; p < 2; p++)
        boff[p] = (uint32_t)((wn * 32 + p * 16 + (lj >> 1) * 8 + lr) * TSTRIDE + (lj & 1) * 16);

    float acc[2][4][4];
    #pragma unroll
    for (int m = 0; m < 2; m++)
        #pragma unroll
        for (int n = 0; n < 4; n++)
            #pragma unroll
            for (int r = 0; r < 4; r++) acc[m][n][r] = 0.f;

    const int NT = K / 32;

    // prologue: stage 0
    cp16(smem + T_AHI + sOff, Ahi + gRow);
    cp16(smem + T_ALO + sOff, Alo + gRow);
    cp16(smem + T_BHI + sOff, Bhi + gRow);
    cp16(smem + T_BLO + sOff, Blo + gRow);
    asm volatile("cp.async.commit_group;");

    for (int t = 0; t < NT; t++) {
        if (t + 1 < NT) {
            char* s1 = smem + ((t + 1) & 1) * STAGE_B;
            size_t g1 = gRow + (size_t)(t + 1) * 32;
            cp16(s1 + T_AHI + sOff, Ahi + g1);
            cp16(s1 + T_ALO + sOff, Alo + g1);
            cp16(s1 + T_BHI + sOff, Bhi + g1);
            cp16(s1 + T_BLO + sOff, Blo + g1);
            asm volatile("cp.async.commit_group;");
            asm volatile("cp.async.wait_group 1;");
        } else {
            asm volatile("cp.async.wait_group 0;");
        }
        __syncthreads();

        const uint32_t sb = smemBase + (t & 1) * STAGE_B;

        #pragma unroll
        for (int ks = 0; ks < 2; ks++) {
            const uint32_t kb = ks * 32;
            uint32_t ah[2][4], al[2][4], bh[4][2], bl[4][2];
            #pragma unroll
            for (int m = 0; m < 2; m++) {
                ldm_x4(ah[m][0], ah[m][1], ah[m][2], ah[m][3], sb + T_AHI + aoff[m] + kb);
                ldm_x4(al[m][0], al[m][1], al[m][2], al[m][3], sb + T_ALO + aoff[m] + kb);
            }
            #pragma unroll
            for (int p = 0; p < 2; p++) {
                ldm_x4(bh[2*p][0], bh[2*p][1], bh[2*p+1][0], bh[2*p+1][1], sb + T_BHI + boff[p] + kb);
                ldm_x4(bl[2*p][0], bl[2*p][1], bl[2*p+1][0], bl[2*p+1][1], sb + T_BLO + boff[p] + kb);
            }
            #pragma unroll
            for (int m = 0; m < 2; m++)
                #pragma unroll
                for (int n = 0; n < 4; n++) {
                    mma_bf16(acc[m][n], ah[m], bh[n]);
                    mma_bf16(acc[m][n], al[m], bh[n]);
                    mma_bf16(acc[m][n], ah[m], bl[n]);
                }
        }
        __syncthreads();
    }

    // epilogue (C fragment layout: rows fr/fr+8, cols (lane&3)*2 +{0,1})
    const int fr  = lane >> 2;
    const int fc2 = (lane & 3) * 2;
    #pragma unroll
    for (int m = 0; m < 2; m++) {
        int row0 = wm * 32 + m * 16 + fr;
        #pragma unroll
        for (int n = 0; n < 4; n++) {
            int col = wn * 32 + n * 8 + fc2;
            float v0 = acc[m][n][0], v1 = acc[m][n][1];
            float v2 = acc[m][n][2], v3 = acc[m][n][3];
            if (BIAS) {
                float b0 = bias[col], b1 = bias[col + 1];
                v0 += b0; v1 += b1; v2 += b0; v3 += b1;
            }
            if (RES) {
                v0 += res[(size_t)row0 * ldc + col];
                v1 += res[(size_t)row0 * ldc + col + 1];
                v2 += res[(size_t)(row0 + 8) * ldc + col];
                v3 += res[(size_t)(row0 + 8) * ldc + col + 1];
            }
            C[(size_t)row0 * ldc + col]           = v0;
            C[(size_t)row0 * ldc + col + 1]       = v1;
            C[(size_t)(row0 + 8) * ldc + col]     = v2;
            C[(size_t)(row0 + 8) * ldc + col + 1] = v3;
        }
    }
}

// generic GEMM with residual (o-proj K=QD, down-proj K=F), N=H
__global__ void __launch_bounds__(512, 1)
mma_gemm_res(int K,
             const bf16* __restrict__ Ahi, const bf16* __restrict__ Alo,
             const bf16* __restrict__ Whi, const bf16* __restrict__ Wlo,
             const float* __restrict__ res, float* __restrict__ C) {
    extern __shared__ char smem[];
    const int bx = blockIdx.x, by = blockIdx.y;
    gemm_body<false, true>(K, H_,
                           Ahi + (size_t)by * 128 * K, Alo + (size_t)by * 128 * K,
                           Whi + (size_t)bx * 128 * K, Wlo + (size_t)bx * 128 * K,
                           nullptr,
                           res + (size_t)by * 128 * H_ + bx * 128,
                           C + (size_t)by * 128 * H_ + bx * 128,
                           smem);
}

// fused QKV projection: grid.x = 16 (12 q blocks, 2 k, 2 v); K = H
__global__ void __launch_bounds__(512, 1)
qkv_kernel(const bf16* __restrict__ Ahi, const bf16* __restrict__ Alo,
           const bf16* __restrict__ whi, const bf16* __restrict__ wlo,   // layer base
           const float* __restrict__ bq, const float* __restrict__ bk,
           const float* __restrict__ bv,
           float* __restrict__ q, float* __restrict__ k, float* __restrict__ v) {
    extern __shared__ char smem[];
    const int bx = blockIdx.x, by = blockIdx.y;
    size_t seg; const float* bp; float* Cp; int ld, n0;
    if (bx < 12)      { seg = OFF_WQ; n0 = bx * 128;        bp = bq; Cp = q; ld = QD;  }
    else if (bx < 14) { seg = OFF_WK; n0 = (bx - 12) * 128; bp = bk; Cp = k; ld = KVD; }
    else              { seg = OFF_WV; n0 = (bx - 14) * 128; bp = bv; Cp = v; ld = KVD; }
    gemm_body<true, false>(H_, ld,
                           Ahi + (size_t)by * 128 * H_, Alo + (size_t)by * 128 * H_,
                           whi + seg + (size_t)n0 * H_, wlo + seg + (size_t)n0 * H_,
                           bp + n0, nullptr,
                           Cp + (size_t)by * 128 * ld + n0,
                           smem);
}

// fused gate+up projection: grid.x = 140 (70 gate, 70 up); K = H, ldc = F
__global__ void __launch_bounds__(512, 1)
gateup_kernel(const bf16* __restrict__ Ahi, const bf16* __restrict__ Alo,
              const bf16* __restrict__ whi, const bf16* __restrict__ wlo,  // layer base
              float* __restrict__ gate, float* __restrict__ up) {
    extern __shared__ char smem[];
    const int bx = blockIdx.x, by = blockIdx.y;
    size_t seg; float* Cp; int n0;
    if (bx < 70) { seg = OFF_WG; n0 = bx * 128;        Cp = gate; }
    else         { seg = OFF_WU; n0 = (bx - 70) * 128; Cp = up;   }
    gemm_body<false, false>(H_, F_,
                            Ahi + (size_t)by * 128 * H_, Alo + (size_t)by * 128 * H_,
                            whi + seg + (size_t)n0 * H_, wlo + seg + (size_t)n0 * H_,
                            nullptr, nullptr,
                            Cp + (size_t)by * 128 * F_ + n0,
                            smem);
}

// ---------------- RoPE (in place) ----------------
__global__ void rope_kernel(float* __restrict__ t, int nh) {
    int row = blockIdx.x;
    int tid = threadIdx.x;          // nh*64
    int hh = tid >> 6, d = tid & 63;
    int s = row % S_;
    float inv = expf(-(float)d * (13.815510557964274f / 64.0f));
    float ang = (float)s * inv;
    float sn, cs; sincosf(ang, &sn, &cs);
    float* p = t + (size_t)row * (nh * DH) + hh * DH + d;
    float x0 = p[0], x1 = p[64];
    p[0]  = x0 * cs - x1 * sn;
    p[64] = x1 * cs + x0 * sn;
}

// ---------------- attention: one block per (b, head, q-row), 128 threads ----------------
__global__ void attn_kernel(const float* __restrict__ q,
                            const float* __restrict__ k,
                            const float* __restrict__ v,
                            const int* __restrict__ mask,
                            bf16* __restrict__ ohi, bf16* __restrict__ olo) {
    int blk = blockIdx.x;
    int b   = blk / (NH * S_);
    int rem = blk % (NH * S_);
    int h   = rem / S_;
    int qi  = rem % S_;
    int kvh = h / (NH / NKV);
    int tid = threadIdx.x;          // 128

    __shared__ float qs[DH];
    __shared__ float sc[128];
    __shared__ float red[128];

    const float* qrow = q + ((size_t)(b * S_ + qi)) * QD + h * DH;
    qs[tid] = qrow[tid];
    __syncthreads();

    float m = -1e30f, l = 0.f, acc = 0.f;
    const float scale = 0.08838834764831845f;

    for (int kc = 0; kc <= qi; kc += 128) {
        int len = min(128, qi + 1 - kc);
        int j = kc + tid;
        float s = -1e30f;
        bool valid = (tid < len) && (mask[b * S_ + j] > 0);
        if (valid) {
            const float4* kr = (const float4*)(k + ((size_t)(b * S_ + j)) * KVD + kvh * DH);
            const float4* qv = (const float4*)qs;
            float sum = 0.f;
            #pragma unroll
            for (int t = 0; t < 32; t++) {
                float4 a = qv[t]; float4 bb = kr[t];
                sum += a.x * bb.x + a.y * bb.y + a.z * bb.z + a.w * bb.w;
            }
            s = sum * scale;
        }
        red[tid] = s; __syncthreads();
        for (int off = 64; off > 0; off >>= 1) {
            if (tid < off) red[tid] = fmaxf(red[tid], red[tid + off]);
            __syncthreads();
        }
        float cmax = red[0];
        __syncthreads();
        float mnew = fmaxf(m, cmax);
        float p = valid ? expf(s - mnew) : 0.f;
        float alpha = expf(m - mnew);
        sc[tid] = p; red[tid] = p; __syncthreads();
        for (int off = 64; off > 0; off >>= 1) {
            if (tid < off) red[tid] += red[tid + off];
            __syncthreads();
        }
        float psum = red[0];
        l = l * alpha + psum;
        m = mnew;
        acc *= alpha;
        const float* vb = v + ((size_t)(b * S_ + kc)) * KVD + kvh * DH + tid;
        for (int jj = 0; jj < len; jj++) acc += sc[jj] * vb[(size_t)jj * KVD];
        __syncthreads();
    }
    float o = acc / l;
    bf16 hh2, ll2; split1(o, hh2, ll2);
    size_t idx = ((size_t)(b * S_ + qi)) * QD + h * DH + tid;
    ohi[idx] = hh2;
    olo[idx] = ll2;
}

// ---------------- silu(gate) * up -> hi/lo bf16 ----------------
__global__ void silu_mul_kernel(const float* __restrict__ g, const float* __restrict__ u,
                                bf16* __restrict__ ohi, bf16* __restrict__ olo, size_t n) {
    size_t i = (size_t)blockIdx.x * blockDim.x + threadIdx.x;
    if (i < n) {
        float x = g[i];
        float s = x / (1.f + expf(-x));
        float v = s * u[i];
        bf16 h, l; split1(v, h, l);
        ohi[i] = h; olo[i] = l;
    }
}

// ---------------- last_hidden gather ----------------
__global__ void last_kernel(const int* __restrict__ mask,
                            const float* __restrict__ hidden,
                            float* __restrict__ out) {
    int b = blockIdx.x;
    int tid = threadIdx.x;  // 256
    __shared__ int red[256];
    int s = 0;
    for (int i = tid; i < S_; i += 256) s += mask[b * S_ + i];
    red[tid] = s; __syncthreads();
    for (int off = 128; off > 0; off >>= 1) {
        if (tid < off) red[tid] += red[tid + off];
        __syncthreads();
    }
    int pos = red[0] - 1;
    const float* hr = hidden + ((size_t)(b * S_ + pos)) * H_;
    for (int i = tid; i < H_; i += 256) out[(size_t)b * H_ + i] = hr[i];
}

extern "C" void kernel_launch(void* const* d_in, const int* in_sizes, int n_in,
                              void* d_out, int out_size) {
    const int*   ids  = (const int*)d_in[0];
    const int*   mask = (const int*)d_in[1];
    const float* emb  = (const float*)d_in[2];
    const float* wq   = (const float*)d_in[3];
    const float* bq   = (const float*)d_in[4];
    const float* wk   = (const float*)d_in[5];
    const float* bk   = (const float*)d_in[6];
    const float* wv   = (const float*)d_in[7];
    const float* bv   = (const float*)d_in[8];
    const float* wo   = (const float*)d_in[9];
    const float* wg   = (const float*)d_in[10];
    const float* wu   = (const float*)d_in[11];
    const float* wd   = (const float*)d_in[12];
    const float* ln1  = (const float*)d_in[13];
    const float* ln2  = (const float*)d_in[14];
    const float* lnf  = (const float*)d_in[15];
    float* out = (float*)d_out;

    float *x, *q, *k, *v, *gate, *up;
    bf16 *hhi, *hlo, *ahi, *alo, *ghi, *glo, *whi, *wlo;
    cudaGetSymbolAddress((void**)&x,    g_x);
    cudaGetSymbolAddress((void**)&hhi,  g_hhi);
    cudaGetSymbolAddress((void**)&hlo,  g_hlo);
    cudaGetSymbolAddress((void**)&q,    g_q);
    cudaGetSymbolAddress((void**)&k,    g_k);
    cudaGetSymbolAddress((void**)&v,    g_v);
    cudaGetSymbolAddress((void**)&ahi,  g_ahi);
    cudaGetSymbolAddress((void**)&alo,  g_alo);
    cudaGetSymbolAddress((void**)&gate, g_gate);
    cudaGetSymbolAddress((void**)&up,   g_up);
    cudaGetSymbolAddress((void**)&ghi,  g_ghi);
    cudaGetSymbolAddress((void**)&glo,  g_glo);
    cudaGetSymbolAddress((void**)&whi,  g_whi);
    cudaGetSymbolAddress((void**)&wlo,  g_wlo);

    static bool attr_set = false;
    if (!attr_set) {
        cudaFuncSetAttribute(qkv_kernel,
                             cudaFuncAttributeMaxDynamicSharedMemorySize, SMEM_BYTES);
        cudaFuncSetAttribute(gateup_kernel,
                             cudaFuncAttributeMaxDynamicSharedMemorySize, SMEM_BYTES);
        cudaFuncSetAttribute(mma_gemm_res,
                             cudaFuncAttributeMaxDynamicSharedMemorySize, SMEM_BYTES);
        attr_set = true;
    }

    // pre-split + transpose all weights (constant inputs)
    dim3 wb(32, 8);
    for (int l = 0; l < L_; l++) {
        bf16* Whi = whi + (size_t)l * WLAYER;
        bf16* Wlo = wlo + (size_t)l * WLAYER;
        wsplit_kernel<<<dim3(QD / 32, H_ / 32), wb>>>(wq + (size_t)l * H_ * QD,  H_, QD,  Whi + OFF_WQ, Wlo + OFF_WQ);
        wsplit_kernel<<<dim3(KVD / 32, H_ / 32), wb>>>(wk + (size_t)l * H_ * KVD, H_, KVD, Whi + OFF_WK, Wlo + OFF_WK);
        wsplit_kernel<<<dim3(KVD / 32, H_ / 32), wb>>>(wv + (size_t)l * H_ * KVD, H_, KVD, Whi + OFF_WV, Wlo + OFF_WV);
        wsplit_kernel<<<dim3(H_ / 32, QD / 32), wb>>>(wo + (size_t)l * QD * H_,  QD, H_,  Whi + OFF_WO, Wlo + OFF_WO);
        wsplit_kernel<<<dim3(F_ / 32, H_ / 32), wb>>>(wg + (size_t)l * H_ * F_,  H_, F_,  Whi + OFF_WG, Wlo + OFF_WG);
        wsplit_kernel<<<dim3(F_ / 32, H_ / 32), wb>>>(wu + (size_t)l * H_ * F_,  H_, F_,  Whi + OFF_WU, Wlo + OFF_WU);
        wsplit_kernel<<<dim3(H_ / 32, F_ / 32), wb>>>(wd + (size_t)l * F_ * H_,  F_, H_,  Whi + OFF_WD, Wlo + OFF_WD);
    }

    embed_kernel<<<ROWS, 256>>>(ids, emb, x);

    for (int l = 0; l < L_; l++) {
        const bf16* Whi = whi + (size_t)l * WLAYER;
        const bf16* Wlo = wlo + (size_t)l * WLAYER;

        rmsnorm_split_kernel<<<ROWS, 256>>>(x, ln1 + (size_t)l * H_, hhi, hlo);

        qkv_kernel<<<dim3(16, ROWS / 128), 512, SMEM_BYTES>>>(
            hhi, hlo, Whi, Wlo,
            bq + (size_t)l * QD, bk + (size_t)l * KVD, bv + (size_t)l * KVD,
            q, k, v);

        rope_kernel<<<ROWS, NH * 64>>>(q, NH);
        rope_kernel<<<ROWS, NKV * 64>>>(k, NKV);

        attn_kernel<<<B_ * NH * S_, 128>>>(q, k, v, mask, ahi, alo);

        mma_gemm_res<<<dim3(H_ / 128, ROWS / 128), 512, SMEM_BYTES>>>(
            QD, ahi, alo, Whi + OFF_WO, Wlo + OFF_WO, x, x);

        rmsnorm_split_kernel<<<ROWS, 256>>>(x, ln2 + (size_t)l * H_, hhi, hlo);

        gateup_kernel<<<dim3(140, ROWS / 128), 512, SMEM_BYTES>>>(
            hhi, hlo, Whi, Wlo, gate, up);

        silu_mul_kernel<<<((size_t)ROWS * F_ + 255) / 256, 256>>>(
            gate, up, ghi, glo, (size_t)ROWS * F_);

        mma_gemm_res<<<dim3(H_ / 128, ROWS / 128), 512, SMEM_BYTES>>>(
            F_, ghi, glo, Whi + OFF_WD, Wlo + OFF_WD, x, x);
    }

    rmsnorm_kernel<<<ROWS, 256>>>(x, lnf, out);
    last_kernel<<<B_, 256>>>(mask, out, out + (size_t)ROWS * H_);
}

// round 10
// speedup vs baseline: 1.9584x; 1.0398x over previous
#include <cuda_runtime.h>
#include <cuda_bf16.h>
#include <math.h>
#include <stdint.h>

// Problem constants (fixed by setup_inputs)
#define B_    2
#define S_    1024
#define ROWS  (B_*S_)       // 2048
#define H_    1536
#define F_    8960
#define L_    2
#define NH    12
#define NKV   2
#define DH    128
#define QD    (NH*DH)       // 1536
#define KVD   (NKV*DH)      // 256
#define EPS_  1e-6f

// Weight-split segment sizes (elements) and per-layer offsets
#define WQ_SZ  (H_*QD)
#define WKV_SZ (H_*KVD)
#define WO_SZ  (QD*H_)
#define WGU_SZ (H_*F_)
#define WD_SZ  (F_*H_)
#define OFF_WQ 0
#define OFF_WK (OFF_WQ + WQ_SZ)
#define OFF_WV (OFF_WK + WKV_SZ)
#define OFF_WO (OFF_WV + WKV_SZ)
#define OFF_WG (OFF_WO + WO_SZ)
#define OFF_WU (OFF_WG + WGU_SZ)
#define OFF_WD (OFF_WU + WGU_SZ)
#define WLAYER (OFF_WD + WD_SZ)

// Scratch (device globals: no allocation allowed)
__device__ float g_x  [ROWS*H_];
__device__ __nv_bfloat16 g_hhi[ROWS*H_];
__device__ __nv_bfloat16 g_hlo[ROWS*H_];
__device__ float g_q  [ROWS*QD];
__device__ float g_k  [ROWS*KVD];
__device__ float g_v  [ROWS*KVD];
__device__ __nv_bfloat16 g_ahi[ROWS*QD];
__device__ __nv_bfloat16 g_alo[ROWS*QD];
__device__ float g_gate[(size_t)ROWS*F_];
__device__ float g_up  [(size_t)ROWS*F_];
__device__ __nv_bfloat16 g_ghi[(size_t)ROWS*F_];
__device__ __nv_bfloat16 g_glo[(size_t)ROWS*F_];
__device__ __nv_bfloat16 g_whi[(size_t)L_*WLAYER];
__device__ __nv_bfloat16 g_wlo[(size_t)L_*WLAYER];

typedef __nv_bfloat16 bf16;

__device__ __forceinline__ void split1(float x, bf16& h, bf16& l) {
    h = __float2bfloat16(x);
    l = __float2bfloat16(x - __bfloat162float(h));
}

// ---------------- weight split + transpose: W[K][N] fp32 -> hi/lo [N][K] bf16 ----------------
__global__ void wsplit_kernel(const float* __restrict__ W, int K, int N,
                              bf16* __restrict__ hi, bf16* __restrict__ lo) {
    __shared__ float t[32][33];
    const int n0 = blockIdx.x * 32, k0 = blockIdx.y * 32;
    const int tx = threadIdx.x, ty = threadIdx.y;   // 32 x 8
    #pragma unroll
    for (int j = 0; j < 4; j++)
        t[ty + 8 * j][tx] = W[(size_t)(k0 + ty + 8 * j) * N + n0 + tx];
    __syncthreads();
    #pragma unroll
    for (int j = 0; j < 4; j++) {
        int n = n0 + ty + 8 * j;
        float v = t[tx][ty + 8 * j];
        bf16 h, l; split1(v, h, l);
        hi[(size_t)n * K + k0 + tx] = h;
        lo[(size_t)n * K + k0 + tx] = l;
    }
}

// ---------------- embedding gather ----------------
__global__ void embed_kernel(const int* __restrict__ ids,
                             const float* __restrict__ emb,
                             float* __restrict__ x) {
    int row = blockIdx.x;
    int id  = ids[row];
    const float* e = emb + (size_t)id * H_;
    float* xr = x + (size_t)row * H_;
    for (int i = threadIdx.x; i < H_; i += blockDim.x) xr[i] = e[i];
}

// ---------------- rmsnorm -> hi/lo bf16 ----------------
__global__ void rmsnorm_split_kernel(const float* __restrict__ x,
                                     const float* __restrict__ w,
                                     bf16* __restrict__ ohi, bf16* __restrict__ olo) {
    int row = blockIdx.x;
    const float* xr = x + (size_t)row * H_;
    int tid = threadIdx.x;            // 256
    float s = 0.f;
    for (int i = tid; i < H_; i += 256) { float v = xr[i]; s += v * v; }
    __shared__ float red[256];
    red[tid] = s; __syncthreads();
    for (int off = 128; off > 0; off >>= 1) {
        if (tid < off) red[tid] += red[tid + off];
        __syncthreads();
    }
    float rs = rsqrtf(red[0] / (float)H_ + EPS_);
    for (int i = tid; i < H_; i += 256) {
        float v = xr[i] * rs * w[i];
        bf16 h, l; split1(v, h, l);
        ohi[(size_t)row * H_ + i] = h;
        olo[(size_t)row * H_ + i] = l;
    }
}

// ---------------- rmsnorm -> fp32 (final) ----------------
__global__ void rmsnorm_kernel(const float* __restrict__ x,
                               const float* __restrict__ w,
                               float* __restrict__ out) {
    int row = blockIdx.x;
    const float* xr = x + (size_t)row * H_;
    int tid = threadIdx.x;
    float s = 0.f;
    for (int i = tid; i < H_; i += 256) { float v = xr[i]; s += v * v; }
    __shared__ float red[256];
    red[tid] = s; __syncthreads();
    for (int off = 128; off > 0; off >>= 1) {
        if (tid < off) red[tid] += red[tid + off];
        __syncthreads();
    }
    float rs = rsqrtf(red[0] / (float)H_ + EPS_);
    float* o = out + (size_t)row * H_;
    for (int i = tid; i < H_; i += 256) o[i] = xr[i] * rs * w[i];
}

// ---------------- MMA + cp.async + ldmatrix helpers ----------------
__device__ __forceinline__ void mma_bf16(float c[4], const uint32_t a[4], const uint32_t b[2]) {
    asm volatile(
        "mma.sync.aligned.m16n8k16.row.col.f32.bf16.bf16.f32 "
        "{%0,%1,%2,%3}, {%4,%5,%6,%7}, {%8,%9}, {%0,%1,%2,%3};"
        : "+f"(c[0]), "+f"(c[1]), "+f"(c[2]), "+f"(c[3])
        : "r"(a[0]), "r"(a[1]), "r"(a[2]), "r"(a[3]), "r"(b[0]), "r"(b[1]));
}

__device__ __forceinline__ void cp16(void* s, const void* g) {
    uint32_t sa = (uint32_t)__cvta_generic_to_shared(s);
    asm volatile("cp.async.cg.shared.global [%0], [%1], 16;" :: "r"(sa), "l"(g));
}

__device__ __forceinline__ void ldm_x4(uint32_t& r0, uint32_t& r1, uint32_t& r2, uint32_t& r3,
                                       uint32_t addr) {
    asm volatile("ldmatrix.sync.aligned.m8n8.x4.shared.b16 {%0,%1,%2,%3}, [%4];"
                 : "=r"(r0), "=r"(r1), "=r"(r2), "=r"(r3) : "r"(addr));
}

// ---------------- bf16x3 GEMM body (pre-split, ldmatrix): 512 threads, BM=BN=128, BK=64 ----------------
#define TSTRIDE 144
#define TILE_B (128 * TSTRIDE)            // 18432
#define STAGE_B (4 * TILE_B)              // 73728
#define SMEM_BYTES (2 * STAGE_B)          // 147456
#define T_AHI 0
#define T_ALO TILE_B
#define T_BHI (2 * TILE_B)
#define T_BLO (3 * TILE_B)

template<bool BIAS, bool RES>
__device__ __forceinline__ void
gemm_body(int K, int ldc,
          const bf16* __restrict__ Ahi, const bf16* __restrict__ Alo,   // + rowblock*K
          const bf16* __restrict__ Bhi, const bf16* __restrict__ Blo,   // + n0*K
          const float* __restrict__ bias,                               // + n0
          const float* __restrict__ res,                                // + rowblock*ldc + n0
          float* __restrict__ C,                                        // + rowblock*ldc + n0
          char* smem) {
    const int tid  = threadIdx.x;
    const int lane = tid & 31;
    const int wid  = tid >> 5;
    const int wm   = wid & 3;
    const int wn   = wid >> 2;

    // staging: thread -> row = tid>>2, two 16B chunks (ch, ch+4) of the 128B row
    const int row = tid >> 2;
    const int ch  = tid & 3;
    const size_t gRow = (size_t)row * K + ch * 8;
    const uint32_t sOff = (uint32_t)(row * TSTRIDE + ch * 16);

    const uint32_t smemBase = (uint32_t)__cvta_generic_to_shared(smem);

    // ldmatrix lane mappings
    const int lj = lane >> 3;     // matrix index 0..3
    const int lr = lane & 7;      // row within matrix
    uint32_t aoff[2];
    #pragma unroll
    for (int m = 0; m < 2; m++)
        aoff[m] = (uint32_t)((wm * 32 + m * 16 + (lj & 1) * 8 + lr) * TSTRIDE + (lj >> 1) * 16);
    uint32_t boff[2];
    #pragma unroll
    for (int p = 0; p < 2; p++)
        boff[p] = (uint32_t)((wn * 32 + p * 16 + (lj >> 1) * 8 + lr) * TSTRIDE + (lj & 1) * 16);

    float acc[2][4][4];
    #pragma unroll
    for (int m = 0; m < 2; m++)
        #pragma unroll
        for (int n = 0; n < 4; n++)
            #pragma unroll
            for (int r = 0; r < 4; r++) acc[m][n][r] = 0.f;

    const int NT = K / 64;

    // prologue: stage 0 (two chunks per tensor per thread)
    #pragma unroll
    for (int c = 0; c < 2; c++) {
        cp16(smem + T_AHI + sOff + c * 64, Ahi + gRow + c * 32);
        cp16(smem + T_ALO + sOff + c * 64, Alo + gRow + c * 32);
        cp16(smem + T_BHI + sOff + c * 64, Bhi + gRow + c * 32);
        cp16(smem + T_BLO + sOff + c * 64, Blo + gRow + c * 32);
    }
    asm volatile("cp.async.commit_group;");

    for (int t = 0; t < NT; t++) {
        if (t + 1 < NT) {
            char* s1 = smem + ((t + 1) & 1) * STAGE_B;
            size_t g1 = gRow + (size_t)(t + 1) * 64;
            #pragma unroll
            for (int c = 0; c < 2; c++) {
                cp16(s1 + T_AHI + sOff + c * 64, Ahi + g1 + c * 32);
                cp16(s1 + T_ALO + sOff + c * 64, Alo + g1 + c * 32);
                cp16(s1 + T_BHI + sOff + c * 64, Bhi + g1 + c * 32);
                cp16(s1 + T_BLO + sOff + c * 64, Blo + g1 + c * 32);
            }
            asm volatile("cp.async.commit_group;");
            asm volatile("cp.async.wait_group 1;");
        } else {
            asm volatile("cp.async.wait_group 0;");
        }
        __syncthreads();

        const uint32_t sb = smemBase + (t & 1) * STAGE_B;

        #pragma unroll
        for (int ks = 0; ks < 4; ks++) {
            const uint32_t kb = ks * 32;
            uint32_t ah[2][4], al[2][4], bh[4][2], bl[4][2];
            #pragma unroll
            for (int m = 0; m < 2; m++) {
                ldm_x4(ah[m][0], ah[m][1], ah[m][2], ah[m][3], sb + T_AHI + aoff[m] + kb);
                ldm_x4(al[m][0], al[m][1], al[m][2], al[m][3], sb + T_ALO + aoff[m] + kb);
            }
            #pragma unroll
            for (int p = 0; p < 2; p++) {
                ldm_x4(bh[2*p][0], bh[2*p][1], bh[2*p+1][0], bh[2*p+1][1], sb + T_BHI + boff[p] + kb);
                ldm_x4(bl[2*p][0], bl[2*p][1], bl[2*p+1][0], bl[2*p+1][1], sb + T_BLO + boff[p] + kb);
            }
            #pragma unroll
            for (int m = 0; m < 2; m++)
                #pragma unroll
                for (int n = 0; n < 4; n++) {
                    mma_bf16(acc[m][n], ah[m], bh[n]);
                    mma_bf16(acc[m][n], al[m], bh[n]);
                    mma_bf16(acc[m][n], ah[m], bl[n]);
                }
        }
        __syncthreads();
    }

    // epilogue
    const int fr  = lane >> 2;
    const int fc2 = (lane & 3) * 2;
    #pragma unroll
    for (int m = 0; m < 2; m++) {
        int row0 = wm * 32 + m * 16 + fr;
        #pragma unroll
        for (int n = 0; n < 4; n++) {
            int col = wn * 32 + n * 8 + fc2;
            float v0 = acc[m][n][0], v1 = acc[m][n][1];
            float v2 = acc[m][n][2], v3 = acc[m][n][3];
            if (BIAS) {
                float b0 = bias[col], b1 = bias[col + 1];
                v0 += b0; v1 += b1; v2 += b0; v3 += b1;
            }
            if (RES) {
                v0 += res[(size_t)row0 * ldc + col];
                v1 += res[(size_t)row0 * ldc + col + 1];
                v2 += res[(size_t)(row0 + 8) * ldc + col];
                v3 += res[(size_t)(row0 + 8) * ldc + col + 1];
            }
            C[(size_t)row0 * ldc + col]           = v0;
            C[(size_t)row0 * ldc + col + 1]       = v1;
            C[(size_t)(row0 + 8) * ldc + col]     = v2;
            C[(size_t)(row0 + 8) * ldc + col + 1] = v3;
        }
    }
}

// generic GEMM with residual (o-proj K=QD, down-proj K=F), N=H
__global__ void __launch_bounds__(512, 1)
mma_gemm_res(int K,
             const bf16* __restrict__ Ahi, const bf16* __restrict__ Alo,
             const bf16* __restrict__ Whi, const bf16* __restrict__ Wlo,
             const float* __restrict__ res, float* __restrict__ C) {
    extern __shared__ char smem[];
    const int bx = blockIdx.x, by = blockIdx.y;
    gemm_body<false, true>(K, H_,
                           Ahi + (size_t)by * 128 * K, Alo + (size_t)by * 128 * K,
                           Whi + (size_t)bx * 128 * K, Wlo + (size_t)bx * 128 * K,
                           nullptr,
                           res + (size_t)by * 128 * H_ + bx * 128,
                           C + (size_t)by * 128 * H_ + bx * 128,
                           smem);
}

// fused QKV projection: grid.x = 16 (12 q blocks, 2 k, 2 v); K = H
__global__ void __launch_bounds__(512, 1)
qkv_kernel(const bf16* __restrict__ Ahi, const bf16* __restrict__ Alo,
           const bf16* __restrict__ whi, const bf16* __restrict__ wlo,   // layer base
           const float* __restrict__ bq, const float* __restrict__ bk,
           const float* __restrict__ bv,
           float* __restrict__ q, float* __restrict__ k, float* __restrict__ v) {
    extern __shared__ char smem[];
    const int bx = blockIdx.x, by = blockIdx.y;
    size_t seg; const float* bp; float* Cp; int ld, n0;
    if (bx < 12)      { seg = OFF_WQ; n0 = bx * 128;        bp = bq; Cp = q; ld = QD;  }
    else if (bx < 14) { seg = OFF_WK; n0 = (bx - 12) * 128; bp = bk; Cp = k; ld = KVD; }
    else              { seg = OFF_WV; n0 = (bx - 14) * 128; bp = bv; Cp = v; ld = KVD; }
    gemm_body<true, false>(H_, ld,
                           Ahi + (size_t)by * 128 * H_, Alo + (size_t)by * 128 * H_,
                           whi + seg + (size_t)n0 * H_, wlo + seg + (size_t)n0 * H_,
                           bp + n0, nullptr,
                           Cp + (size_t)by * 128 * ld + n0,
                           smem);
}

// fused gate+up projection: grid.x = 140 (70 gate, 70 up); K = H, ldc = F
__global__ void __launch_bounds__(512, 1)
gateup_kernel(const bf16* __restrict__ Ahi, const bf16* __restrict__ Alo,
              const bf16* __restrict__ whi, const bf16* __restrict__ wlo,  // layer base
              float* __restrict__ gate, float* __restrict__ up) {
    extern __shared__ char smem[];
    const int bx = blockIdx.x, by = blockIdx.y;
    size_t seg; float* Cp; int n0;
    if (bx < 70) { seg = OFF_WG; n0 = bx * 128;        Cp = gate; }
    else         { seg = OFF_WU; n0 = (bx - 70) * 128; Cp = up;   }
    gemm_body<false, false>(H_, F_,
                            Ahi + (size_t)by * 128 * H_, Alo + (size_t)by * 128 * H_,
                            whi + seg + (size_t)n0 * H_, wlo + seg + (size_t)n0 * H_,
                            nullptr, nullptr,
                            Cp + (size_t)by * 128 * F_ + n0,
                            smem);
}

// ---------------- RoPE (in place) ----------------
__global__ void rope_kernel(float* __restrict__ t, int nh) {
    int row = blockIdx.x;
    int tid = threadIdx.x;          // nh*64
    int hh = tid >> 6, d = tid & 63;
    int s = row % S_;
    float inv = expf(-(float)d * (13.815510557964274f / 64.0f));
    float ang = (float)s * inv;
    float sn, cs; sincosf(ang, &sn, &cs);
    float* p = t + (size_t)row * (nh * DH) + hh * DH + d;
    float x0 = p[0], x1 = p[64];
    p[0]  = x0 * cs - x1 * sn;
    p[64] = x1 * cs + x0 * sn;
}

// ---------------- attention: one block per (b, head, q-row), 128 threads, shfl reductions ----------------
__global__ void attn_kernel(const float* __restrict__ q,
                            const float* __restrict__ k,
                            const float* __restrict__ v,
                            const int* __restrict__ mask,
                            bf16* __restrict__ ohi, bf16* __restrict__ olo) {
    int blk = blockIdx.x;
    int b   = blk / (NH * S_);
    int rem = blk % (NH * S_);
    int h   = rem / S_;
    int qi  = rem % S_;
    int kvh = h / (NH / NKV);
    int tid = threadIdx.x;          // 128
    int lane = tid & 31, wrp = tid >> 5;

    __shared__ float qs[DH];
    __shared__ float sc[128];
    __shared__ float red[8];

    const float* qrow = q + ((size_t)(b * S_ + qi)) * QD + h * DH;
    qs[tid] = qrow[tid];
    __syncthreads();

    float m = -1e30f, l = 0.f, acc = 0.f;
    const float scale = 0.08838834764831845f;

    for (int kc = 0; kc <= qi; kc += 128) {
        int len = min(128, qi + 1 - kc);
        int j = kc + tid;
        float s = -1e30f;
        bool valid = (tid < len) && (mask[b * S_ + j] > 0);
        if (valid) {
            const float4* kr = (const float4*)(k + ((size_t)(b * S_ + j)) * KVD + kvh * DH);
            const float4* qv = (const float4*)qs;
            float sum = 0.f;
            #pragma unroll
            for (int t = 0; t < 32; t++) {
                float4 a = qv[t]; float4 bb = kr[t];
                sum += a.x * bb.x + a.y * bb.y + a.z * bb.z + a.w * bb.w;
            }
            s = sum * scale;
        }
        // warp max -> block max via 4-slot combine
        float wmax = s;
        #pragma unroll
        for (int off = 16; off > 0; off >>= 1)
            wmax = fmaxf(wmax, __shfl_xor_sync(0xFFFFFFFF, wmax, off));
        if (lane == 0) red[wrp] = wmax;
        __syncthreads();
        float cmax = fmaxf(fmaxf(red[0], red[1]), fmaxf(red[2], red[3]));
        float mnew = fmaxf(m, cmax);
        float p = valid ? __expf(s - mnew) : 0.f;
        sc[tid] = p;
        float wsum = p;
        #pragma unroll
        for (int off = 16; off > 0; off >>= 1)
            wsum += __shfl_xor_sync(0xFFFFFFFF, wsum, off);
        if (lane == 0) red[4 + wrp] = wsum;
        __syncthreads();
        float psum = red[4] + red[5] + red[6] + red[7];

        float alpha = __expf(m - mnew);
        l = l * alpha + psum;
        m = mnew;
        acc *= alpha;
        const float* vb = v + ((size_t)(b * S_ + kc)) * KVD + kvh * DH + tid;
        int jj = 0;
        for (; jj + 4 <= len; jj += 4) {
            acc += sc[jj]     * vb[(size_t)jj * KVD];
            acc += sc[jj + 1] * vb[(size_t)(jj + 1) * KVD];
            acc += sc[jj + 2] * vb[(size_t)(jj + 2) * KVD];
            acc += sc[jj + 3] * vb[(size_t)(jj + 3) * KVD];
        }
        for (; jj < len; jj++) acc += sc[jj] * vb[(size_t)jj * KVD];
        __syncthreads();
    }
    float o = acc / l;
    bf16 hh2, ll2; split1(o, hh2, ll2);
    size_t idx = ((size_t)(b * S_ + qi)) * QD + h * DH + tid;
    ohi[idx] = hh2;
    olo[idx] = ll2;
}

// ---------------- silu(gate) * up -> hi/lo bf16 ----------------
__global__ void silu_mul_kernel(const float* __restrict__ g, const float* __restrict__ u,
                                bf16* __restrict__ ohi, bf16* __restrict__ olo, size_t n) {
    size_t i = (size_t)blockIdx.x * blockDim.x + threadIdx.x;
    if (i < n) {
        float x = g[i];
        float s = x / (1.f + __expf(-x));
        float v = s * u[i];
        bf16 h, l; split1(v, h, l);
        ohi[i] = h; olo[i] = l;
    }
}

// ---------------- last_hidden gather ----------------
__global__ void last_kernel(const int* __restrict__ mask,
                            const float* __restrict__ hidden,
                            float* __restrict__ out) {
    int b = blockIdx.x;
    int tid = threadIdx.x;  // 256
    __shared__ int red[256];
    int s = 0;
    for (int i = tid; i < S_; i += 256) s += mask[b * S_ + i];
    red[tid] = s; __syncthreads();
    for (int off = 128; off > 0; off >>= 1) {
        if (tid < off) red[tid] += red[tid + off];
        __syncthreads();
    }
    int pos = red[0] - 1;
    const float* hr = hidden + ((size_t)(b * S_ + pos)) * H_;
    for (int i = tid; i < H_; i += 256) out[(size_t)b * H_ + i] = hr[i];
}

extern "C" void kernel_launch(void* const* d_in, const int* in_sizes, int n_in,
                              void* d_out, int out_size) {
    const int*   ids  = (const int*)d_in[0];
    const int*   mask = (const int*)d_in[1];
    const float* emb  = (const float*)d_in[2];
    const float* wq   = (const float*)d_in[3];
    const float* bq   = (const float*)d_in[4];
    const float* wk   = (const float*)d_in[5];
    const float* bk   = (const float*)d_in[6];
    const float* wv   = (const float*)d_in[7];
    const float* bv   = (const float*)d_in[8];
    const float* wo   = (const float*)d_in[9];
    const float* wg   = (const float*)d_in[10];
    const float* wu   = (const float*)d_in[11];
    const float* wd   = (const float*)d_in[12];
    const float* ln1  = (const float*)d_in[13];
    const float* ln2  = (const float*)d_in[14];
    const float* lnf  = (const float*)d_in[15];
    float* out = (float*)d_out;

    float *x, *q, *k, *v, *gate, *up;
    bf16 *hhi, *hlo, *ahi, *alo, *ghi, *glo, *whi, *wlo;
    cudaGetSymbolAddress((void**)&x,    g_x);
    cudaGetSymbolAddress((void**)&hhi,  g_hhi);
    cudaGetSymbolAddress((void**)&hlo,  g_hlo);
    cudaGetSymbolAddress((void**)&q,    g_q);
    cudaGetSymbolAddress((void**)&k,    g_k);
    cudaGetSymbolAddress((void**)&v,    g_v);
    cudaGetSymbolAddress((void**)&ahi,  g_ahi);
    cudaGetSymbolAddress((void**)&alo,  g_alo);
    cudaGetSymbolAddress((void**)&gate, g_gate);
    cudaGetSymbolAddress((void**)&up,   g_up);
    cudaGetSymbolAddress((void**)&ghi,  g_ghi);
    cudaGetSymbolAddress((void**)&glo,  g_glo);
    cudaGetSymbolAddress((void**)&whi,  g_whi);
    cudaGetSymbolAddress((void**)&wlo,  g_wlo);

    static bool attr_set = false;
    if (!attr_set) {
        cudaFuncSetAttribute(qkv_kernel,
                             cudaFuncAttributeMaxDynamicSharedMemorySize, SMEM_BYTES);
        cudaFuncSetAttribute(gateup_kernel,
                             cudaFuncAttributeMaxDynamicSharedMemorySize, SMEM_BYTES);
        cudaFuncSetAttribute(mma_gemm_res,
                             cudaFuncAttributeMaxDynamicSharedMemorySize, SMEM_BYTES);
        attr_set = true;
    }

    // pre-split + transpose all weights (constant inputs)
    dim3 wb(32, 8);
    for (int l = 0; l < L_; l++) {
        bf16* Whi = whi + (size_t)l * WLAYER;
        bf16* Wlo = wlo + (size_t)l * WLAYER;
        wsplit_kernel<<<dim3(QD / 32, H_ / 32), wb>>>(wq + (size_t)l * H_ * QD,  H_, QD,  Whi + OFF_WQ, Wlo + OFF_WQ);
        wsplit_kernel<<<dim3(KVD / 32, H_ / 32), wb>>>(wk + (size_t)l * H_ * KVD, H_, KVD, Whi + OFF_WK, Wlo + OFF_WK);
        wsplit_kernel<<<dim3(KVD / 32, H_ / 32), wb>>>(wv + (size_t)l * H_ * KVD, H_, KVD, Whi + OFF_WV, Wlo + OFF_WV);
        wsplit_kernel<<<dim3(H_ / 32, QD / 32), wb>>>(wo + (size_t)l * QD * H_,  QD, H_,  Whi + OFF_WO, Wlo + OFF_WO);
        wsplit_kernel<<<dim3(F_ / 32, H_ / 32), wb>>>(wg + (size_t)l * H_ * F_,  H_, F_,  Whi + OFF_WG, Wlo + OFF_WG);
        wsplit_kernel<<<dim3(F_ / 32, H_ / 32), wb>>>(wu + (size_t)l * H_ * F_,  H_, F_,  Whi + OFF_WU, Wlo + OFF_WU);
        wsplit_kernel<<<dim3(H_ / 32, F_ / 32), wb>>>(wd + (size_t)l * F_ * H_,  F_, H_,  Whi + OFF_WD, Wlo + OFF_WD);
    }

    embed_kernel<<<ROWS, 256>>>(ids, emb, x);

    for (int l = 0; l < L_; l++) {
        const bf16* Whi = whi + (size_t)l * WLAYER;
        const bf16* Wlo = wlo + (size_t)l * WLAYER;

        rmsnorm_split_kernel<<<ROWS, 256>>>(x, ln1 + (size_t)l * H_, hhi, hlo);

        qkv_kernel<<<dim3(16, ROWS / 128), 512, SMEM_BYTES>>>(
            hhi, hlo, Whi, Wlo,
            bq + (size_t)l * QD, bk + (size_t)l * KVD, bv + (size_t)l * KVD,
            q, k, v);

        rope_kernel<<<ROWS, NH * 64>>>(q, NH);
        rope_kernel<<<ROWS, NKV * 64>>>(k, NKV);

        attn_kernel<<<B_ * NH * S_, 128>>>(q, k, v, mask, ahi, alo);

        mma_gemm_res<<<dim3(H_ / 128, ROWS / 128), 512, SMEM_BYTES>>>(
            QD, ahi, alo, Whi + OFF_WO, Wlo + OFF_WO, x, x);

        rmsnorm_split_kernel<<<ROWS, 256>>>(x, ln2 + (size_t)l * H_, hhi, hlo);

        gateup_kernel<<<dim3(140, ROWS / 128), 512, SMEM_BYTES>>>(
            hhi, hlo, Whi, Wlo, gate, up);

        silu_mul_kernel<<<((size_t)ROWS * F_ + 255) / 256, 256>>>(
            gate, up, ghi, glo, (size_t)ROWS * F_);

        mma_gemm_res<<<dim3(H_ / 128, ROWS / 128), 512, SMEM_BYTES>>>(
            F_, ghi, glo, Whi + OFF_WD, Wlo + OFF_WD, x, x);
    }

    rmsnorm_kernel<<<ROWS, 256>>>(x, lnf, out);
    last_kernel<<<B_, 256>>>(mask, out, out + (size_t)ROWS * H_);
}